// round 14
// baseline (speedup 1.0000x reference)
#include <cuda_runtime.h>
#include <cuda_bf16.h>
#include <cstdint>

#define N_NODES 100000
#define N_EDGES 1600000
#define IN_F 128
#define HID_F 128
#define OUT_F 64
#define EPS 1e-5f

#if defined(__CUDA_ARCH_FEAT_SM103_ALL) || defined(__CUDA_ARCH_FEAT_SM100_ALL) || defined(__CUDA_ARCH_FEAT_SM101_ALL)
#define HAS_TCGEN05 1
#else
#define HAS_TCGEN05 0
#endif

// ============================ PTX helpers (sm_103a) ============================
__device__ __forceinline__ uint32_t elect_one() {
    uint32_t pred;
    asm volatile("{\n\t.reg .pred p;\n\telect.sync _|p, 0xFFFFFFFF;\n\tselp.b32 %0, 1, 0, p;\n\t}"
                 : "=r"(pred));
    return pred;
}
__device__ __forceinline__ uint32_t smem_u32(const void* p) {
    uint32_t a;
    asm("{ .reg .u64 t; cvta.to.shared.u64 t, %1; cvt.u32.u64 %0, t; }" : "=r"(a) : "l"(p));
    return a;
}
#define SW128(off) ((off) ^ (((off) >> 3) & 0x70))

static constexpr uint64_t DESC_BASE_SW128 =
    (uint64_t(2) << 61) | (uint64_t(1) << 46) | (uint64_t(64) << 32) | (uint64_t(1) << 16);
__device__ __forceinline__ uint64_t make_desc(uint32_t addr) {
    return DESC_BASE_SW128 | ((uint64_t)(addr >> 4) & 0x3FFF);
}

#if HAS_TCGEN05
#define TC_ALLOC(smem_addr, n) \
    asm volatile("tcgen05.alloc.cta_group::1.sync.aligned.shared::cta.b32 [%0], %1;" \
                 :: "r"(smem_addr), "r"((uint32_t)(n)) : "memory")
#define TC_DEALLOC(tmem, n) \
    asm volatile("tcgen05.dealloc.cta_group::1.sync.aligned.b32 %0, %1;" :: "r"(tmem), "r"((uint32_t)(n)))
#define TC_RELINQ() asm volatile("tcgen05.relinquish_alloc_permit.cta_group::1.sync.aligned;")
#define TC_COMMIT(mbar) \
    asm volatile("tcgen05.commit.cta_group::1.mbarrier::arrive::one.shared::cluster.b64 [%0];" \
                 :: "r"(mbar) : "memory")
#define TC_FENCE_BEFORE() asm volatile("tcgen05.fence::before_thread_sync;" ::: "memory")
#define TC_FENCE_AFTER()  asm volatile("tcgen05.fence::after_thread_sync;" ::: "memory")
#define TC_WAIT_ST()      asm volatile("tcgen05.wait::st.sync.aligned;" ::: "memory")
#define TC_WAIT_LD()      asm volatile("tcgen05.wait::ld.sync.aligned;" ::: "memory")
#define FENCE_ASYNC()     asm volatile("fence.proxy.async.shared::cta;" ::: "memory")
#define MBAR_INIT(a, c) \
    asm volatile("mbarrier.init.shared.b64 [%0], %1;" :: "r"(a), "r"((uint32_t)(c)) : "memory")
#define MBAR_INVAL(a) asm volatile("mbarrier.inval.shared.b64 [%0];" :: "r"(a) : "memory")
#define MBAR_WAIT(mbar, parity) do {                                              \
    uint32_t _m = (mbar), _p = (parity), _done;                                   \
    asm volatile("{\n\t.reg .pred p;\n\t"                                         \
        "mbarrier.try_wait.parity.acquire.cta.shared::cta.b64 p, [%1], %2;\n\t"   \
        "selp.b32 %0, 1, 0, p;\n\t}" : "=r"(_done) : "r"(_m), "r"(_p) : "memory");\
    if (!_done) {                                                                 \
        asm volatile("{\n\t.reg .pred P1;\n\t"                                    \
            "WL_%=:\n\t"                                                          \
            "mbarrier.try_wait.parity.acquire.cta.shared::cta.b64 P1, [%0], %1, 0x989680;\n\t" \
            "@P1 bra.uni WD_%=;\n\tbra.uni WL_%=;\n\tWD_%=:\n\t}"                 \
            :: "r"(_m), "r"(_p) : "memory");                                      \
    } } while (0)

#define TC_ST_X16(addr, r) \
    asm volatile( \
        "tcgen05.st.sync.aligned.32x32b.x16.b32 [%0], " \
        "{%1, %2, %3, %4, %5, %6, %7, %8, %9, %10, %11, %12, %13, %14, %15, %16};" \
        :: "r"(addr), \
           "r"((r)[0]),  "r"((r)[1]),  "r"((r)[2]),  "r"((r)[3]), \
           "r"((r)[4]),  "r"((r)[5]),  "r"((r)[6]),  "r"((r)[7]), \
           "r"((r)[8]),  "r"((r)[9]),  "r"((r)[10]), "r"((r)[11]), \
           "r"((r)[12]), "r"((r)[13]), "r"((r)[14]), "r"((r)[15]) \
        : "memory")

#define TC_LD_X32(r, addr) \
    asm volatile( \
        "tcgen05.ld.sync.aligned.32x32b.x32.b32 " \
        "{%0, %1, %2, %3, %4, %5, %6, %7, %8, %9, %10, %11, %12, %13, %14, %15, " \
        " %16, %17, %18, %19, %20, %21, %22, %23, %24, %25, %26, %27, %28, %29, %30, %31}, [%32];" \
        : "=r"((r)[0]),  "=r"((r)[1]),  "=r"((r)[2]),  "=r"((r)[3]), \
          "=r"((r)[4]),  "=r"((r)[5]),  "=r"((r)[6]),  "=r"((r)[7]), \
          "=r"((r)[8]),  "=r"((r)[9]),  "=r"((r)[10]), "=r"((r)[11]), \
          "=r"((r)[12]), "=r"((r)[13]), "=r"((r)[14]), "=r"((r)[15]), \
          "=r"((r)[16]), "=r"((r)[17]), "=r"((r)[18]), "=r"((r)[19]), \
          "=r"((r)[20]), "=r"((r)[21]), "=r"((r)[22]), "=r"((r)[23]), \
          "=r"((r)[24]), "=r"((r)[25]), "=r"((r)[26]), "=r"((r)[27]), \
          "=r"((r)[28]), "=r"((r)[29]), "=r"((r)[30]), "=r"((r)[31]) \
        : "r"(addr))

__device__ __forceinline__ void mma_f16_ts(uint32_t d_tmem, uint32_t a_tmem, uint64_t b_desc,
                                           uint32_t idesc, bool en) {
    uint32_t e = en ? 1u : 0u;
    asm volatile(
        "{\n\t.reg .pred p;\n\tsetp.ne.u32 p, %5, 0;\n\t"
        "tcgen05.mma.cta_group::1.kind::f16 [%0], [%1], %2, %3, {%4, %4, %4, %4}, p;\n\t}"
        :: "r"(d_tmem), "r"(a_tmem), "l"(b_desc), "r"(idesc), "r"(0u), "r"(e) : "memory");
}
#endif // HAS_TCGEN05

// ============================ scratch (zero-initialized at module load) ============================
__device__ __align__(16) float g_agg[(size_t)N_NODES * HID_F];
__device__ __align__(16) float g_h1 [(size_t)N_NODES * HID_F];
__device__ int   g_deg_i[N_NODES + 1];    // [N_NODES] = allocation counter; re-zeroed by cleanup
__device__ int   g_rowstart[N_NODES];
__device__ int   g_cursor[N_NODES];
__device__ int   g_csr_src[N_EDGES];
__device__ float g_fsum[HID_F];
__device__ float g_fsumsq[HID_F];
__device__ __align__(16) float g_scale1[HID_F];
__device__ __align__(16) float g_shift1[HID_F];
__device__ __align__(16) float g_scale2[OUT_F];
__device__ __align__(16) float g_shift2[OUT_F];
__device__ __nv_bfloat16 g_B1hi[128 * 256];
__device__ __nv_bfloat16 g_B1lo[128 * 256];
__device__ __nv_bfloat16 g_B2hi[64 * 256];
__device__ __nv_bfloat16 g_B2lo[64 * 256];

// ============================ CSR build ============================
__global__ void hist_kernel(const int* __restrict__ dst, int E) {
    int e = blockIdx.x * blockDim.x + threadIdx.x;
    if (e < E) atomicAdd(&g_deg_i[dst[e]], 1);
}
// slot allocation + BN-stat zero + weight split (fused)
__global__ void alloc_kernel(int M,
                             const float* __restrict__ Ws1, const float* __restrict__ Wn1,
                             const float* __restrict__ Ws2, const float* __restrict__ Wn2) {
    int i = blockIdx.x * blockDim.x + threadIdx.x;
    if (i < M) {
        int d = g_deg_i[i];
        int s = atomicAdd(&g_deg_i[N_NODES], d);
        g_rowstart[i] = s;
        g_cursor[i]   = s;
    }
    if (blockIdx.x == 0 && threadIdx.x < HID_F) {
        g_fsum[threadIdx.x] = 0.f;
        g_fsumsq[threadIdx.x] = 0.f;
    }
    const int n1 = 128 * 256;
    if (i < n1) {
        int n = i >> 8, k = i & 255;
        float w = (k < 128) ? Ws1[(size_t)k * 128 + n] : Wn1[(size_t)(k - 128) * 128 + n];
        __nv_bfloat16 h = __float2bfloat16(w);
        g_B1hi[(size_t)n * 256 + k] = h;
        g_B1lo[(size_t)n * 256 + k] = __float2bfloat16(w - __bfloat162float(h));
    } else if (i < n1 + 64 * 256) {
        int j = i - n1;
        int n = j >> 8, k = j & 255;
        float w = (k < 128) ? Ws2[(size_t)k * 64 + n] : Wn2[(size_t)(k - 128) * 64 + n];
        __nv_bfloat16 h = __float2bfloat16(w);
        g_B2hi[(size_t)n * 256 + k] = h;
        g_B2lo[(size_t)n * 256 + k] = __float2bfloat16(w - __bfloat162float(h));
    }
}
__global__ void fill_kernel(const int* __restrict__ src, const int* __restrict__ dst, int E) {
    int e = blockIdx.x * blockDim.x + threadIdx.x;
    if (e < E) {
        int slot = atomicAdd(&g_cursor[dst[e]], 1);
        g_csr_src[slot] = src[e];
    }
}
// re-zero g_deg_i for the next replay (runs after the last reader, gather2)
__global__ void cleanup_kernel() {
    int i = blockIdx.x * blockDim.x + threadIdx.x;
    if (i <= N_NODES) g_deg_i[i] = 0;
}

// ============================ gather aggregation (warp per node, 4-wide — R11 shape) ============================
__device__ __forceinline__ void bn_relu4(float4& v, const float4& sc, const float4& sh) {
    v.x = fmaxf(fmaf(v.x, sc.x, sh.x), 0.0f);
    v.y = fmaxf(fmaf(v.y, sc.y, sh.y), 0.0f);
    v.z = fmaxf(fmaf(v.z, sc.z, sh.z), 0.0f);
    v.w = fmaxf(fmaf(v.w, sc.w, sh.w), 0.0f);
}
template <bool BN>
__global__ void __launch_bounds__(256)
gather_kernel(const float* __restrict__ h, int M) {
    int node = blockIdx.x * 8 + (threadIdx.x >> 5);
    int lane = threadIdx.x & 31;
    if (node >= M) return;
    int beg = g_rowstart[node];
    int cnt = g_deg_i[node];
    float4 acc = make_float4(0.f, 0.f, 0.f, 0.f);
    float4 sc, sh;
    if (BN) {
        sc = *(const float4*)(g_scale1 + lane * 4);
        sh = *(const float4*)(g_shift1 + lane * 4);
    }
    for (int j0 = 0; j0 < cnt; j0 += 32) {
        int rem = cnt - j0;
        int lim = rem < 32 ? rem : 32;
        int myidx = (lane < lim) ? __ldg(&g_csr_src[beg + j0 + lane]) : 0;
        int jj = 0;
        for (; jj + 4 <= lim; jj += 4) {
            int s0 = __shfl_sync(0xffffffffu, myidx, jj);
            int s1 = __shfl_sync(0xffffffffu, myidx, jj + 1);
            int s2 = __shfl_sync(0xffffffffu, myidx, jj + 2);
            int s3 = __shfl_sync(0xffffffffu, myidx, jj + 3);
            float4 v0 = __ldg((const float4*)(h + (size_t)s0 * 128) + lane);
            float4 v1 = __ldg((const float4*)(h + (size_t)s1 * 128) + lane);
            float4 v2 = __ldg((const float4*)(h + (size_t)s2 * 128) + lane);
            float4 v3 = __ldg((const float4*)(h + (size_t)s3 * 128) + lane);
            if (BN) { bn_relu4(v0, sc, sh); bn_relu4(v1, sc, sh); bn_relu4(v2, sc, sh); bn_relu4(v3, sc, sh); }
            acc.x += (v0.x + v1.x) + (v2.x + v3.x);
            acc.y += (v0.y + v1.y) + (v2.y + v3.y);
            acc.z += (v0.z + v1.z) + (v2.z + v3.z);
            acc.w += (v0.w + v1.w) + (v2.w + v3.w);
        }
        for (; jj < lim; ++jj) {
            int s0 = __shfl_sync(0xffffffffu, myidx, jj);
            float4 v0 = __ldg((const float4*)(h + (size_t)s0 * 128) + lane);
            if (BN) bn_relu4(v0, sc, sh);
            acc.x += v0.x; acc.y += v0.y; acc.z += v0.z; acc.w += v0.w;
        }
    }
    float r = 1.0f / (float)(cnt > 0 ? cnt : 1);
    acc.x *= r; acc.y *= r; acc.z *= r; acc.w *= r;
    *(float4*)(g_agg + (size_t)node * 128 + lane * 4) = acc;
}

// ============================ persistent pipelined tcgen05 TS GEMM (R11) ============================
#define STAGE_WORDS (128 * 65)
template <int NOUT, bool BNIN>
__global__ void __launch_bounds__(512) __cluster_dims__(1, 1, 1)
gemm_tc(const float* __restrict__ A, const float* __restrict__ Aneigh,
        const __nv_bfloat16* __restrict__ Bhi, const __nv_bfloat16* __restrict__ Blo,
        const float* __restrict__ bias, float* __restrict__ C, int M, int ntiles) {
#if HAS_TCGEN05
    extern __shared__ unsigned char smem_raw[];
    __shared__ uint32_t s_tmem[1];
    __shared__ __align__(8) unsigned long long s_mbar[1];

    const int tid = threadIdx.x;
    const int wid = tid >> 5;
    const int lane = tid & 31;
    constexpr int BBYTES = 8 * NOUT * 128;

    unsigned char* sB = (unsigned char*)(((uintptr_t)smem_raw + 1023) & ~(uintptr_t)1023);
    uint32_t* hiTile = (uint32_t*)(sB + BBYTES);
    uint32_t* loTile = hiTile + STAGE_WORDS;
    const uint32_t sB_addr = smem_u32(sB);
    const uint32_t tptr_addr = smem_u32(s_tmem);
    const uint32_t mbar_addr = smem_u32(s_mbar);
    const uint32_t warp_off = (uint32_t)(wid & 3) << 21;

    if (tid == 0) MBAR_INIT(mbar_addr, 1);

    // ---- B load ONCE ----
    for (int idx = tid; idx < 8 * NOUT * 8; idx += 512) {
        int c = idx / (NOUT * 8);
        int rem = idx - c * (NOUT * 8);
        int n = rem >> 3;
        int q = rem & 7;
        const __nv_bfloat16* s = ((q & 4) ? Blo : Bhi) + (size_t)n * 256 + c * 32 + (q & 3) * 8;
        uint4 val = *(const uint4*)s;
        uint32_t off = (uint32_t)(n * 128 + ((q & 4) ? 64 : 0) + (q & 3) * 16);
        *(uint4*)(sB + c * (NOUT * 128) + SW128(off)) = val;
    }

    if (wid == 0) TC_ALLOC(tptr_addr, 512);
    __syncthreads();
    if (wid == 0) TC_RELINQ();
    uint32_t tmem;
    asm volatile("ld.shared.b32 %0, [%1];" : "=r"(tmem) : "r"(tptr_addr));
    FENCE_ASYNC();
    __syncthreads();

    constexpr uint32_t IDESC =
        (1u << 4) | (1u << 7) | (1u << 10) | ((uint32_t)(NOUT / 8) << 17) | (8u << 24);
    const uint32_t d_tmem = tmem + 256;
    const int myrow = tid & 127;
    const int sub = tid >> 7;
    int ph = 0;

    auto stage = [&](int row0, int p) {
        const float* __restrict__ srcM = p ? Aneigh : A;
        #pragma unroll
        for (int it = 0; it < 8; ++it) {
            int idx = tid + it * 512;
            int r = idx >> 5;
            int q = idx & 31;
            int gr = row0 + r;
            float4 v = make_float4(0.f, 0.f, 0.f, 0.f);
            if (gr < M) {
                v = *(const float4*)(srcM + (size_t)gr * 128 + q * 4);
                if (BNIN && p == 0) {
                    float4 sc = *(const float4*)(g_scale1 + q * 4);
                    float4 sh = *(const float4*)(g_shift1 + q * 4);
                    bn_relu4(v, sc, sh);
                }
            }
            uint32_t ux = __float_as_uint(v.x), uy = __float_as_uint(v.y);
            uint32_t uz = __float_as_uint(v.z), uw = __float_as_uint(v.w);
            uint32_t hi0 = __byte_perm(ux, uy, 0x7632);
            uint32_t hi1 = __byte_perm(uz, uw, 0x7632);
            float lx = v.x - __uint_as_float(ux & 0xFFFF0000u);
            float ly = v.y - __uint_as_float(uy & 0xFFFF0000u);
            float lz = v.z - __uint_as_float(uz & 0xFFFF0000u);
            float lw = v.w - __uint_as_float(uw & 0xFFFF0000u);
            uint32_t lo0 = __byte_perm(__float_as_uint(lx), __float_as_uint(ly), 0x7632);
            uint32_t lo1 = __byte_perm(__float_as_uint(lz), __float_as_uint(lw), 0x7632);
            int base = r * 65 + q * 2;
            hiTile[base] = hi0; hiTile[base + 1] = hi1;
            loTile[base] = lo0; loTile[base + 1] = lo1;
        }
    };
    auto tmemst = [&](int p) {
        uint32_t hr[16], lr[16];
        int base = myrow * 65 + sub * 16;
        #pragma unroll
        for (int i = 0; i < 16; ++i) { hr[i] = hiTile[base + i]; lr[i] = loTile[base + i]; }
        uint32_t col = (uint32_t)(p * 64 + sub * 16);
        TC_ST_X16(tmem + col + warp_off, hr);
        TC_ST_X16(tmem + 128 + col + warp_off, lr);
    };
    auto epilogue = [&](int row0) {
        const int cset = wid >> 2;
        if (cset >= NOUT / 32) return;
        const int cbase = cset * 32;
        const int row = row0 + (wid & 3) * 32 + lane;
        const bool valid = (row < M);
        uint32_t dr[32];
        TC_LD_X32(dr, d_tmem + cbase);
        TC_WAIT_LD();
        float s[32], q[32];
        #pragma unroll
        for (int j = 0; j < 32; ++j) {
            float y = __uint_as_float(dr[j]) + __ldg(&bias[cbase + j]);
            s[j] = valid ? y : 0.f;
            q[j] = valid ? y * y : 0.f;
            dr[j] = __float_as_uint(y);
        }
        if (valid) {
            #pragma unroll
            for (int j = 0; j < 32; j += 4)
                *(float4*)(C + (size_t)row * NOUT + cbase + j) =
                    make_float4(__uint_as_float(dr[j]), __uint_as_float(dr[j + 1]),
                                __uint_as_float(dr[j + 2]), __uint_as_float(dr[j + 3]));
        }
        #pragma unroll
        for (int half = 16; half >= 1; half >>= 1) {
            bool up = (lane & half) != 0;
            #pragma unroll
            for (int j = 0; j < half; ++j) {
                float ssend = up ? s[j] : s[j + half];
                float qsend = up ? q[j] : q[j + half];
                float srecv = __shfl_xor_sync(0xffffffffu, ssend, half);
                float qrecv = __shfl_xor_sync(0xffffffffu, qsend, half);
                s[j] = (up ? s[j + half] : s[j]) + srecv;
                q[j] = (up ? q[j + half] : q[j]) + qrecv;
            }
        }
        atomicAdd(&g_fsum[cbase + lane], s[0]);
        atomicAdd(&g_fsumsq[cbase + lane], q[0]);
    };

    int tile = blockIdx.x;
    int prev_row0 = 0;
    bool have_prev = false;
    if (tile < ntiles) stage(tile * 128, 0);
    __syncthreads();

    while (tile < ntiles) {
        const int row0 = tile * 128;
        if (have_prev) {
            MBAR_WAIT(mbar_addr, ph);
            ph ^= 1;
            TC_FENCE_AFTER();
            epilogue(prev_row0);
        }
        __syncthreads();
        tmemst(0);
        __syncthreads();
        stage(row0, 1);
        __syncthreads();
        tmemst(1);
        TC_WAIT_ST();
        TC_FENCE_BEFORE();
        __syncthreads();
        if (wid == 0) {
            TC_FENCE_AFTER();
            if (elect_one()) {
                #pragma unroll
                for (int t = 0; t < 16; ++t) {
                    int c = t >> 1, ss = t & 1;
                    uint64_t dhi = make_desc(sB_addr + c * (NOUT * 128)) + 2 * ss;
                    uint64_t dlo = dhi + 4;
                    mma_f16_ts(d_tmem, tmem + t * 8,       dhi, IDESC, t > 0);
                    mma_f16_ts(d_tmem, tmem + t * 8,       dlo, IDESC, true);
                    mma_f16_ts(d_tmem, tmem + 128 + t * 8, dhi, IDESC, true);
                }
                TC_COMMIT(mbar_addr);
            }
        }
        prev_row0 = row0;
        have_prev = true;
        tile += gridDim.x;
        if (tile < ntiles) stage(tile * 128, 0);   // overlaps MMA in flight
        __syncthreads();
    }
    if (have_prev) {
        MBAR_WAIT(mbar_addr, ph);
        ph ^= 1;
        TC_FENCE_AFTER();
        epilogue(prev_row0);
    }
    __syncthreads();
    if (tid == 0) MBAR_INVAL(mbar_addr);
    if (wid == 0) TC_DEALLOC(tmem, 512);
#else
    // SIMT fallback (plain compute_103 PTX pass; never selected at runtime)
    const int tid = threadIdx.x;
    for (int tile = blockIdx.x; tile < ntiles; tile += gridDim.x) {
        const int row = tile * 128 + (tid & 127);
        if (tid < 128 && row < M) {
            float acc[NOUT];
            #pragma unroll
            for (int n = 0; n < NOUT; ++n) acc[n] = 0.f;
            for (int k = 0; k < 256; ++k) {
                float a;
                if (k < 128) {
                    a = A[(size_t)row * 128 + k];
                    if (BNIN) a = fmaxf(fmaf(a, g_scale1[k], g_shift1[k]), 0.f);
                } else {
                    a = Aneigh[(size_t)row * 128 + (k - 128)];
                }
                for (int n = 0; n < NOUT; ++n) {
                    float w = __bfloat162float(Bhi[(size_t)n * 256 + k]) +
                              __bfloat162float(Blo[(size_t)n * 256 + k]);
                    acc[n] += a * w;
                }
            }
            for (int n = 0; n < NOUT; ++n) {
                float y = acc[n] + bias[n];
                C[(size_t)row * NOUT + n] = y;
                atomicAdd(&g_fsum[n], y);
                atomicAdd(&g_fsumsq[n], y * y);
            }
        }
    }
#endif
}

// ============================ BN prep (zeroes stats after reading) ============================
template <int COLS, int LAYER>
__global__ void bnprep_kernel(const float* __restrict__ gamma,
                              const float* __restrict__ beta, int M) {
    int c = threadIdx.x;
    if (c >= COLS) return;
    float invM = 1.0f / (float)M;
    float mu = g_fsum[c] * invM;
    float var = g_fsumsq[c] * invM - mu * mu;
    if (var < 0.f) var = 0.f;
    float sc = gamma[c] * rsqrtf(var + EPS);
    if (LAYER == 1) { g_scale1[c] = sc; g_shift1[c] = beta[c] - mu * sc; }
    else            { g_scale2[c] = sc; g_shift2[c] = beta[c] - mu * sc; }
    g_fsum[c] = 0.f;
    g_fsumsq[c] = 0.f;
}
__global__ void apply_out_kernel(float* __restrict__ h, long total) {
    long i = ((long)blockIdx.x * blockDim.x + threadIdx.x) * 4;
    long stride = (long)gridDim.x * blockDim.x * 4;
    for (; i < total; i += stride) {
        int c = (int)(i & (OUT_F - 1));
        float4 v = *(float4*)(h + i);
        float4 sc = *(const float4*)(g_scale2 + c);
        float4 sh = *(const float4*)(g_shift2 + c);
        v.x = fmaf(v.x, sc.x, sh.x);
        v.y = fmaf(v.y, sc.y, sh.y);
        v.z = fmaf(v.z, sc.z, sh.z);
        v.w = fmaf(v.w, sc.w, sh.w);
        *(float4*)(h + i) = v;
    }
}

// ============================ launch ============================
extern "C" void kernel_launch(void* const* d_in, const int* in_sizes, int n_in,
                              void* d_out, int out_size) {
    const float* features = (const float*)d_in[0];
    const int*   src      = (const int*)d_in[1];
    const int*   dst      = (const int*)d_in[2];
    const float* W_self1  = (const float*)d_in[3];
    const float* W_neigh1 = (const float*)d_in[4];
    const float* b1       = (const float*)d_in[5];
    const float* gamma1   = (const float*)d_in[6];
    const float* beta1    = (const float*)d_in[7];
    const float* W_self2  = (const float*)d_in[8];
    const float* W_neigh2 = (const float*)d_in[9];
    const float* b2       = (const float*)d_in[10];
    const float* gamma2   = (const float*)d_in[11];
    const float* beta2    = (const float*)d_in[12];
    float* out = (float*)d_out;

    const int M = in_sizes[0] / IN_F;
    const int E = in_sizes[1];

    void *p_agg, *p_h1, *p_b1hi, *p_b1lo, *p_b2hi, *p_b2lo;
    cudaGetSymbolAddress(&p_agg, g_agg);
    cudaGetSymbolAddress(&p_h1, g_h1);
    cudaGetSymbolAddress(&p_b1hi, g_B1hi);
    cudaGetSymbolAddress(&p_b1lo, g_B1lo);
    cudaGetSymbolAddress(&p_b2hi, g_B2hi);
    cudaGetSymbolAddress(&p_b2lo, g_B2lo);
    float* agg = (float*)p_agg;
    float* h1  = (float*)p_h1;

    const int eb = (E + 255) / 256;
    const int gatherBlocks = (M + 7) / 8;
    const int ntiles = (M + 127) / 128;
    const int gemmGrid = ntiles < 148 ? ntiles : 148;

    const int stageBytes = 2 * STAGE_WORDS * 4;                 // 66560
    const int smem1 = 8 * HID_F * 128 + stageBytes + 1024;     // 198656
    const int smem2 = 8 * OUT_F * 128 + stageBytes + 1024;     // 133120
    cudaFuncSetAttribute(gemm_tc<HID_F, false>,
                         cudaFuncAttributeMaxDynamicSharedMemorySize, smem1);
    cudaFuncSetAttribute(gemm_tc<OUT_F, true>,
                         cudaFuncAttributeMaxDynamicSharedMemorySize, smem2);

    // CSR build — g_deg_i is zero on entry (module load / tail cleanup of prior replay)
    hist_kernel<<<eb, 256>>>(dst, E);
    alloc_kernel<<<(M + 255) / 256, 256>>>(M, W_self1, W_neigh1, W_self2, W_neigh2);
    fill_kernel<<<eb, 256>>>(src, dst, E);

    // ---- layer 1 ----
    gather_kernel<false><<<gatherBlocks, 256>>>(features, M);
    gemm_tc<HID_F, false><<<gemmGrid, 512, smem1>>>(features, agg,   // <- sampled launch (5th)
        (const __nv_bfloat16*)p_b1hi, (const __nv_bfloat16*)p_b1lo, b1, h1, M, ntiles);
    bnprep_kernel<HID_F, 1><<<1, HID_F>>>(gamma1, beta1, M);

    // ---- layer 2 ----
    gather_kernel<true><<<gatherBlocks, 256>>>(h1, M);
    gemm_tc<OUT_F, true><<<gemmGrid, 512, smem2>>>(h1, agg,
        (const __nv_bfloat16*)p_b2hi, (const __nv_bfloat16*)p_b2lo, b2, out, M, ntiles);
    bnprep_kernel<OUT_F, 2><<<1, OUT_F>>>(gamma2, beta2, M);
    apply_out_kernel<<<2048, 256>>>(out, (long)M * OUT_F);

    // reset deg/counter for next replay (last reader was gather2)
    cleanup_kernel<<<(N_NODES + 256) / 256, 256>>>();
}

// round 15
// speedup vs baseline: 1.3449x; 1.3449x over previous
#include <cuda_runtime.h>
#include <cuda_bf16.h>
#include <cstdint>

#define N_NODES 100000
#define N_EDGES 1600000
#define IN_F 128
#define HID_F 128
#define OUT_F 64
#define EPS 1e-5f

#if defined(__CUDA_ARCH_FEAT_SM103_ALL) || defined(__CUDA_ARCH_FEAT_SM100_ALL) || defined(__CUDA_ARCH_FEAT_SM101_ALL)
#define HAS_TCGEN05 1
#else
#define HAS_TCGEN05 0
#endif

// ============================ PTX helpers (sm_103a) ============================
__device__ __forceinline__ uint32_t elect_one() {
    uint32_t pred;
    asm volatile("{\n\t.reg .pred p;\n\telect.sync _|p, 0xFFFFFFFF;\n\tselp.b32 %0, 1, 0, p;\n\t}"
                 : "=r"(pred));
    return pred;
}
__device__ __forceinline__ uint32_t smem_u32(const void* p) {
    uint32_t a;
    asm("{ .reg .u64 t; cvta.to.shared.u64 t, %1; cvt.u32.u64 %0, t; }" : "=r"(a) : "l"(p));
    return a;
}
#define SW128(off) ((off) ^ (((off) >> 3) & 0x70))

static constexpr uint64_t DESC_BASE_SW128 =
    (uint64_t(2) << 61) | (uint64_t(1) << 46) | (uint64_t(64) << 32) | (uint64_t(1) << 16);
__device__ __forceinline__ uint64_t make_desc(uint32_t addr) {
    return DESC_BASE_SW128 | ((uint64_t)(addr >> 4) & 0x3FFF);
}

#if HAS_TCGEN05
#define TC_ALLOC(smem_addr, n) \
    asm volatile("tcgen05.alloc.cta_group::1.sync.aligned.shared::cta.b32 [%0], %1;" \
                 :: "r"(smem_addr), "r"((uint32_t)(n)) : "memory")
#define TC_DEALLOC(tmem, n) \
    asm volatile("tcgen05.dealloc.cta_group::1.sync.aligned.b32 %0, %1;" :: "r"(tmem), "r"((uint32_t)(n)))
#define TC_RELINQ() asm volatile("tcgen05.relinquish_alloc_permit.cta_group::1.sync.aligned;")
#define TC_COMMIT(mbar) \
    asm volatile("tcgen05.commit.cta_group::1.mbarrier::arrive::one.shared::cluster.b64 [%0];" \
                 :: "r"(mbar) : "memory")
#define TC_FENCE_BEFORE() asm volatile("tcgen05.fence::before_thread_sync;" ::: "memory")
#define TC_FENCE_AFTER()  asm volatile("tcgen05.fence::after_thread_sync;" ::: "memory")
#define TC_WAIT_ST()      asm volatile("tcgen05.wait::st.sync.aligned;" ::: "memory")
#define TC_WAIT_LD()      asm volatile("tcgen05.wait::ld.sync.aligned;" ::: "memory")
#define FENCE_ASYNC()     asm volatile("fence.proxy.async.shared::cta;" ::: "memory")
#define MBAR_INIT(a, c) \
    asm volatile("mbarrier.init.shared.b64 [%0], %1;" :: "r"(a), "r"((uint32_t)(c)) : "memory")
#define MBAR_INVAL(a) asm volatile("mbarrier.inval.shared.b64 [%0];" :: "r"(a) : "memory")
#define MBAR_WAIT(mbar, parity) do {                                              \
    uint32_t _m = (mbar), _p = (parity), _done;                                   \
    asm volatile("{\n\t.reg .pred p;\n\t"                                         \
        "mbarrier.try_wait.parity.acquire.cta.shared::cta.b64 p, [%1], %2;\n\t"   \
        "selp.b32 %0, 1, 0, p;\n\t}" : "=r"(_done) : "r"(_m), "r"(_p) : "memory");\
    if (!_done) {                                                                 \
        asm volatile("{\n\t.reg .pred P1;\n\t"                                    \
            "WL_%=:\n\t"                                                          \
            "mbarrier.try_wait.parity.acquire.cta.shared::cta.b64 P1, [%0], %1, 0x989680;\n\t" \
            "@P1 bra.uni WD_%=;\n\tbra.uni WL_%=;\n\tWD_%=:\n\t}"                 \
            :: "r"(_m), "r"(_p) : "memory");                                      \
    } } while (0)

#define TC_ST_X16(addr, r) \
    asm volatile( \
        "tcgen05.st.sync.aligned.32x32b.x16.b32 [%0], " \
        "{%1, %2, %3, %4, %5, %6, %7, %8, %9, %10, %11, %12, %13, %14, %15, %16};" \
        :: "r"(addr), \
           "r"((r)[0]),  "r"((r)[1]),  "r"((r)[2]),  "r"((r)[3]), \
           "r"((r)[4]),  "r"((r)[5]),  "r"((r)[6]),  "r"((r)[7]), \
           "r"((r)[8]),  "r"((r)[9]),  "r"((r)[10]), "r"((r)[11]), \
           "r"((r)[12]), "r"((r)[13]), "r"((r)[14]), "r"((r)[15]) \
        : "memory")

#define TC_LD_X32(r, addr) \
    asm volatile( \
        "tcgen05.ld.sync.aligned.32x32b.x32.b32 " \
        "{%0, %1, %2, %3, %4, %5, %6, %7, %8, %9, %10, %11, %12, %13, %14, %15, " \
        " %16, %17, %18, %19, %20, %21, %22, %23, %24, %25, %26, %27, %28, %29, %30, %31}, [%32];" \
        : "=r"((r)[0]),  "=r"((r)[1]),  "=r"((r)[2]),  "=r"((r)[3]), \
          "=r"((r)[4]),  "=r"((r)[5]),  "=r"((r)[6]),  "=r"((r)[7]), \
          "=r"((r)[8]),  "=r"((r)[9]),  "=r"((r)[10]), "=r"((r)[11]), \
          "=r"((r)[12]), "=r"((r)[13]), "=r"((r)[14]), "=r"((r)[15]), \
          "=r"((r)[16]), "=r"((r)[17]), "=r"((r)[18]), "=r"((r)[19]), \
          "=r"((r)[20]), "=r"((r)[21]), "=r"((r)[22]), "=r"((r)[23]), \
          "=r"((r)[24]), "=r"((r)[25]), "=r"((r)[26]), "=r"((r)[27]), \
          "=r"((r)[28]), "=r"((r)[29]), "=r"((r)[30]), "=r"((r)[31]) \
        : "r"(addr))

__device__ __forceinline__ void mma_f16_ts(uint32_t d_tmem, uint32_t a_tmem, uint64_t b_desc,
                                           uint32_t idesc, bool en) {
    uint32_t e = en ? 1u : 0u;
    asm volatile(
        "{\n\t.reg .pred p;\n\tsetp.ne.u32 p, %5, 0;\n\t"
        "tcgen05.mma.cta_group::1.kind::f16 [%0], [%1], %2, %3, {%4, %4, %4, %4}, p;\n\t}"
        :: "r"(d_tmem), "r"(a_tmem), "l"(b_desc), "r"(idesc), "r"(0u), "r"(e) : "memory");
}
#endif // HAS_TCGEN05

// ============================ scratch ============================
__device__ __align__(16) float g_agg[(size_t)N_NODES * HID_F];
__device__ __align__(16) float g_h1 [(size_t)N_NODES * HID_F];
__device__ int   g_deg_i[N_NODES + 1];    // [N_NODES] = allocation counter
__device__ int   g_rowstart[N_NODES];
__device__ int   g_cursor[N_NODES];
__device__ int   g_csr_src[N_EDGES];
__device__ float g_fsum[HID_F];
__device__ float g_fsumsq[HID_F];
__device__ __align__(16) float g_scale1[HID_F];
__device__ __align__(16) float g_shift1[HID_F];
__device__ __align__(16) float g_scale2[OUT_F];
__device__ __align__(16) float g_shift2[OUT_F];
__device__ __nv_bfloat16 g_B1hi[128 * 256];
__device__ __nv_bfloat16 g_B1lo[128 * 256];
__device__ __nv_bfloat16 g_B2hi[64 * 256];
__device__ __nv_bfloat16 g_B2lo[64 * 256];

// ============================ CSR build ============================
__global__ void hist_kernel(const int* __restrict__ dst, int E) {
    int e = blockIdx.x * blockDim.x + threadIdx.x;
    if (e < E) atomicAdd(&g_deg_i[dst[e]], 1);
}
// slot allocation + BN-stat zero + weight split (fused)
__global__ void alloc_kernel(int M,
                             const float* __restrict__ Ws1, const float* __restrict__ Wn1,
                             const float* __restrict__ Ws2, const float* __restrict__ Wn2) {
    int i = blockIdx.x * blockDim.x + threadIdx.x;
    if (i < M) {
        int d = g_deg_i[i];
        int s = atomicAdd(&g_deg_i[N_NODES], d);
        g_rowstart[i] = s;
        g_cursor[i]   = s;
    }
    if (blockIdx.x == 0 && threadIdx.x < HID_F) {
        g_fsum[threadIdx.x] = 0.f;
        g_fsumsq[threadIdx.x] = 0.f;
    }
    const int n1 = 128 * 256;
    if (i < n1) {
        int n = i >> 8, k = i & 255;
        float w = (k < 128) ? Ws1[(size_t)k * 128 + n] : Wn1[(size_t)(k - 128) * 128 + n];
        __nv_bfloat16 h = __float2bfloat16(w);
        g_B1hi[(size_t)n * 256 + k] = h;
        g_B1lo[(size_t)n * 256 + k] = __float2bfloat16(w - __bfloat162float(h));
    } else if (i < n1 + 64 * 256) {
        int j = i - n1;
        int n = j >> 8, k = j & 255;
        float w = (k < 128) ? Ws2[(size_t)k * 64 + n] : Wn2[(size_t)(k - 128) * 64 + n];
        __nv_bfloat16 h = __float2bfloat16(w);
        g_B2hi[(size_t)n * 256 + k] = h;
        g_B2lo[(size_t)n * 256 + k] = __float2bfloat16(w - __bfloat162float(h));
    }
}
__global__ void fill_kernel(const int* __restrict__ src, const int* __restrict__ dst, int E) {
    int e = blockIdx.x * blockDim.x + threadIdx.x;
    if (e < E) {
        int slot = atomicAdd(&g_cursor[dst[e]], 1);
        g_csr_src[slot] = src[e];
    }
}

// ============================ gather aggregation (warp per node) ============================
__device__ __forceinline__ void bn_relu4(float4& v, const float4& sc, const float4& sh) {
    v.x = fmaxf(fmaf(v.x, sc.x, sh.x), 0.0f);
    v.y = fmaxf(fmaf(v.y, sc.y, sh.y), 0.0f);
    v.z = fmaxf(fmaf(v.z, sc.z, sh.z), 0.0f);
    v.w = fmaxf(fmaf(v.w, sc.w, sh.w), 0.0f);
}
template <bool BN>
__global__ void __launch_bounds__(256)
gather_kernel(const float* __restrict__ h, int M) {
    int node = blockIdx.x * 8 + (threadIdx.x >> 5);
    int lane = threadIdx.x & 31;
    if (node >= M) return;
    int beg = g_rowstart[node];
    int cnt = g_deg_i[node];
    float4 acc = make_float4(0.f, 0.f, 0.f, 0.f);
    float4 sc, sh;
    if (BN) {
        sc = *(const float4*)(g_scale1 + lane * 4);
        sh = *(const float4*)(g_shift1 + lane * 4);
    }
    for (int j0 = 0; j0 < cnt; j0 += 32) {
        int rem = cnt - j0;
        int lim = rem < 32 ? rem : 32;
        int myidx = (lane < lim) ? __ldg(&g_csr_src[beg + j0 + lane]) : 0;
        int jj = 0;
        for (; jj + 4 <= lim; jj += 4) {
            int s0 = __shfl_sync(0xffffffffu, myidx, jj);
            int s1 = __shfl_sync(0xffffffffu, myidx, jj + 1);
            int s2 = __shfl_sync(0xffffffffu, myidx, jj + 2);
            int s3 = __shfl_sync(0xffffffffu, myidx, jj + 3);
            float4 v0 = __ldg((const float4*)(h + (size_t)s0 * 128) + lane);
            float4 v1 = __ldg((const float4*)(h + (size_t)s1 * 128) + lane);
            float4 v2 = __ldg((const float4*)(h + (size_t)s2 * 128) + lane);
            float4 v3 = __ldg((const float4*)(h + (size_t)s3 * 128) + lane);
            if (BN) { bn_relu4(v0, sc, sh); bn_relu4(v1, sc, sh); bn_relu4(v2, sc, sh); bn_relu4(v3, sc, sh); }
            acc.x += (v0.x + v1.x) + (v2.x + v3.x);
            acc.y += (v0.y + v1.y) + (v2.y + v3.y);
            acc.z += (v0.z + v1.z) + (v2.z + v3.z);
            acc.w += (v0.w + v1.w) + (v2.w + v3.w);
        }
        for (; jj < lim; ++jj) {
            int s0 = __shfl_sync(0xffffffffu, myidx, jj);
            float4 v0 = __ldg((const float4*)(h + (size_t)s0 * 128) + lane);
            if (BN) bn_relu4(v0, sc, sh);
            acc.x += v0.x; acc.y += v0.y; acc.z += v0.z; acc.w += v0.w;
        }
    }
    float r = 1.0f / (float)(cnt > 0 ? cnt : 1);
    acc.x *= r; acc.y *= r; acc.z *= r; acc.w *= r;
    *(float4*)(g_agg + (size_t)node * 128 + lane * 4) = acc;
}

// ============================ persistent pipelined tcgen05 TS GEMM ============================
// C[M,NOUT] = A'[M,128] @ Wself + agg[M,128] @ Wneigh + bias ; A' = BNIN ? relu(bn(A)) : A
// Persistent 148 CTAs; B loaded once; TMEM alloc'd once; per-tile parity-alternating commit.
// Pipeline: stage pass0 of tile t+1 issued right after commit(t).
// TMEM: A-hi [0,128), A-lo [128,256), D at 256.
#define STAGE_WORDS (128 * 65)
template <int NOUT, bool BNIN>
__global__ void __launch_bounds__(512) __cluster_dims__(1, 1, 1)
gemm_tc(const float* __restrict__ A, const float* __restrict__ Aneigh,
        const __nv_bfloat16* __restrict__ Bhi, const __nv_bfloat16* __restrict__ Blo,
        const float* __restrict__ bias, float* __restrict__ C, int M, int ntiles) {
#if HAS_TCGEN05
    extern __shared__ unsigned char smem_raw[];
    __shared__ uint32_t s_tmem[1];
    __shared__ __align__(8) unsigned long long s_mbar[1];

    const int tid = threadIdx.x;
    const int wid = tid >> 5;
    const int lane = tid & 31;
    constexpr int BBYTES = 8 * NOUT * 128;

    unsigned char* sB = (unsigned char*)(((uintptr_t)smem_raw + 1023) & ~(uintptr_t)1023);
    uint32_t* hiTile = (uint32_t*)(sB + BBYTES);
    uint32_t* loTile = hiTile + STAGE_WORDS;
    const uint32_t sB_addr = smem_u32(sB);
    const uint32_t tptr_addr = smem_u32(s_tmem);
    const uint32_t mbar_addr = smem_u32(s_mbar);
    const uint32_t warp_off = (uint32_t)(wid & 3) << 21;

    if (tid == 0) MBAR_INIT(mbar_addr, 1);

    // ---- B load ONCE ----
    for (int idx = tid; idx < 8 * NOUT * 8; idx += 512) {
        int c = idx / (NOUT * 8);
        int rem = idx - c * (NOUT * 8);
        int n = rem >> 3;
        int q = rem & 7;
        const __nv_bfloat16* s = ((q & 4) ? Blo : Bhi) + (size_t)n * 256 + c * 32 + (q & 3) * 8;
        uint4 val = *(const uint4*)s;
        uint32_t off = (uint32_t)(n * 128 + ((q & 4) ? 64 : 0) + (q & 3) * 16);
        *(uint4*)(sB + c * (NOUT * 128) + SW128(off)) = val;
    }

    if (wid == 0) TC_ALLOC(tptr_addr, 512);
    __syncthreads();
    if (wid == 0) TC_RELINQ();
    uint32_t tmem;
    asm volatile("ld.shared.b32 %0, [%1];" : "=r"(tmem) : "r"(tptr_addr));
    FENCE_ASYNC();
    __syncthreads();

    constexpr uint32_t IDESC =
        (1u << 4) | (1u << 7) | (1u << 10) | ((uint32_t)(NOUT / 8) << 17) | (8u << 24);
    const uint32_t d_tmem = tmem + 256;
    const int myrow = tid & 127;
    const int sub = tid >> 7;
    int ph = 0;

    auto stage = [&](int row0, int p) {
        const float* __restrict__ srcM = p ? Aneigh : A;
        #pragma unroll
        for (int it = 0; it < 8; ++it) {
            int idx = tid + it * 512;
            int r = idx >> 5;
            int q = idx & 31;
            int gr = row0 + r;
            float4 v = make_float4(0.f, 0.f, 0.f, 0.f);
            if (gr < M) {
                v = *(const float4*)(srcM + (size_t)gr * 128 + q * 4);
                if (BNIN && p == 0) {
                    float4 sc = *(const float4*)(g_scale1 + q * 4);
                    float4 sh = *(const float4*)(g_shift1 + q * 4);
                    bn_relu4(v, sc, sh);
                }
            }
            uint32_t ux = __float_as_uint(v.x), uy = __float_as_uint(v.y);
            uint32_t uz = __float_as_uint(v.z), uw = __float_as_uint(v.w);
            uint32_t hi0 = __byte_perm(ux, uy, 0x7632);
            uint32_t hi1 = __byte_perm(uz, uw, 0x7632);
            float lx = v.x - __uint_as_float(ux & 0xFFFF0000u);
            float ly = v.y - __uint_as_float(uy & 0xFFFF0000u);
            float lz = v.z - __uint_as_float(uz & 0xFFFF0000u);
            float lw = v.w - __uint_as_float(uw & 0xFFFF0000u);
            uint32_t lo0 = __byte_perm(__float_as_uint(lx), __float_as_uint(ly), 0x7632);
            uint32_t lo1 = __byte_perm(__float_as_uint(lz), __float_as_uint(lw), 0x7632);
            int base = r * 65 + q * 2;
            hiTile[base] = hi0; hiTile[base + 1] = hi1;
            loTile[base] = lo0; loTile[base + 1] = lo1;
        }
    };
    auto tmemst = [&](int p) {
        uint32_t hr[16], lr[16];
        int base = myrow * 65 + sub * 16;
        #pragma unroll
        for (int i = 0; i < 16; ++i) { hr[i] = hiTile[base + i]; lr[i] = loTile[base + i]; }
        uint32_t col = (uint32_t)(p * 64 + sub * 16);
        TC_ST_X16(tmem + col + warp_off, hr);
        TC_ST_X16(tmem + 128 + col + warp_off, lr);
    };
    auto epilogue = [&](int row0) {
        const int cset = wid >> 2;
        if (cset >= NOUT / 32) return;
        const int cbase = cset * 32;
        const int row = row0 + (wid & 3) * 32 + lane;
        const bool valid = (row < M);
        uint32_t dr[32];
        TC_LD_X32(dr, d_tmem + cbase);
        TC_WAIT_LD();
        float s[32], q[32];
        #pragma unroll
        for (int j = 0; j < 32; ++j) {
            float y = __uint_as_float(dr[j]) + __ldg(&bias[cbase + j]);
            s[j] = valid ? y : 0.f;
            q[j] = valid ? y * y : 0.f;
            dr[j] = __float_as_uint(y);
        }
        if (valid) {
            #pragma unroll
            for (int j = 0; j < 32; j += 4)
                *(float4*)(C + (size_t)row * NOUT + cbase + j) =
                    make_float4(__uint_as_float(dr[j]), __uint_as_float(dr[j + 1]),
                                __uint_as_float(dr[j + 2]), __uint_as_float(dr[j + 3]));
        }
        #pragma unroll
        for (int half = 16; half >= 1; half >>= 1) {
            bool up = (lane & half) != 0;
            #pragma unroll
            for (int j = 0; j < half; ++j) {
                float ssend = up ? s[j] : s[j + half];
                float qsend = up ? q[j] : q[j + half];
                float srecv = __shfl_xor_sync(0xffffffffu, ssend, half);
                float qrecv = __shfl_xor_sync(0xffffffffu, qsend, half);
                s[j] = (up ? s[j + half] : s[j]) + srecv;
                q[j] = (up ? q[j + half] : q[j]) + qrecv;
            }
        }
        atomicAdd(&g_fsum[cbase + lane], s[0]);
        atomicAdd(&g_fsumsq[cbase + lane], q[0]);
    };

    int tile = blockIdx.x;
    int prev_row0 = 0;
    bool have_prev = false;
    if (tile < ntiles) stage(tile * 128, 0);
    __syncthreads();

    while (tile < ntiles) {
        const int row0 = tile * 128;
        if (have_prev) {
            MBAR_WAIT(mbar_addr, ph);
            ph ^= 1;
            TC_FENCE_AFTER();
            epilogue(prev_row0);
        }
        __syncthreads();
        tmemst(0);
        __syncthreads();
        stage(row0, 1);
        __syncthreads();
        tmemst(1);
        TC_WAIT_ST();
        TC_FENCE_BEFORE();
        __syncthreads();
        if (wid == 0) {
            TC_FENCE_AFTER();
            if (elect_one()) {
                #pragma unroll
                for (int t = 0; t < 16; ++t) {
                    int c = t >> 1, ss = t & 1;
                    uint64_t dhi = make_desc(sB_addr + c * (NOUT * 128)) + 2 * ss;
                    uint64_t dlo = dhi + 4;
                    mma_f16_ts(d_tmem, tmem + t * 8,       dhi, IDESC, t > 0);
                    mma_f16_ts(d_tmem, tmem + t * 8,       dlo, IDESC, true);
                    mma_f16_ts(d_tmem, tmem + 128 + t * 8, dhi, IDESC, true);
                }
                TC_COMMIT(mbar_addr);
            }
        }
        prev_row0 = row0;
        have_prev = true;
        tile += gridDim.x;
        if (tile < ntiles) stage(tile * 128, 0);   // overlaps MMA in flight
        __syncthreads();
    }
    if (have_prev) {
        MBAR_WAIT(mbar_addr, ph);
        ph ^= 1;
        TC_FENCE_AFTER();
        epilogue(prev_row0);
    }
    __syncthreads();
    if (tid == 0) MBAR_INVAL(mbar_addr);
    if (wid == 0) TC_DEALLOC(tmem, 512);
#else
    // SIMT fallback (plain compute_103 PTX pass; never selected at runtime)
    const int tid = threadIdx.x;
    for (int tile = blockIdx.x; tile < ntiles; tile += gridDim.x) {
        const int row = tile * 128 + (tid & 127);
        if (tid < 128 && row < M) {
            float acc[NOUT];
            #pragma unroll
            for (int n = 0; n < NOUT; ++n) acc[n] = 0.f;
            for (int k = 0; k < 256; ++k) {
                float a;
                if (k < 128) {
                    a = A[(size_t)row * 128 + k];
                    if (BNIN) a = fmaxf(fmaf(a, g_scale1[k], g_shift1[k]), 0.f);
                } else {
                    a = Aneigh[(size_t)row * 128 + (k - 128)];
                }
                for (int n = 0; n < NOUT; ++n) {
                    float w = __bfloat162float(Bhi[(size_t)n * 256 + k]) +
                              __bfloat162float(Blo[(size_t)n * 256 + k]);
                    acc[n] += a * w;
                }
            }
            for (int n = 0; n < NOUT; ++n) {
                float y = acc[n] + bias[n];
                C[(size_t)row * NOUT + n] = y;
                atomicAdd(&g_fsum[n], y);
                atomicAdd(&g_fsumsq[n], y * y);
            }
        }
    }
#endif
}

// ============================ BN prep (zeroes stats after reading) ============================
template <int COLS, int LAYER>
__global__ void bnprep_kernel(const float* __restrict__ gamma,
                              const float* __restrict__ beta, int M) {
    int c = threadIdx.x;
    if (c >= COLS) return;
    float invM = 1.0f / (float)M;
    float mu = g_fsum[c] * invM;
    float var = g_fsumsq[c] * invM - mu * mu;
    if (var < 0.f) var = 0.f;
    float sc = gamma[c] * rsqrtf(var + EPS);
    if (LAYER == 1) { g_scale1[c] = sc; g_shift1[c] = beta[c] - mu * sc; }
    else            { g_scale2[c] = sc; g_shift2[c] = beta[c] - mu * sc; }
    g_fsum[c] = 0.f;
    g_fsumsq[c] = 0.f;
}
__global__ void apply_out_kernel(float* __restrict__ h, long total) {
    long i = ((long)blockIdx.x * blockDim.x + threadIdx.x) * 4;
    long stride = (long)gridDim.x * blockDim.x * 4;
    for (; i < total; i += stride) {
        int c = (int)(i & (OUT_F - 1));
        float4 v = *(float4*)(h + i);
        float4 sc = *(const float4*)(g_scale2 + c);
        float4 sh = *(const float4*)(g_shift2 + c);
        v.x = fmaf(v.x, sc.x, sh.x);
        v.y = fmaf(v.y, sc.y, sh.y);
        v.z = fmaf(v.z, sc.z, sh.z);
        v.w = fmaf(v.w, sc.w, sh.w);
        *(float4*)(h + i) = v;
    }
}

// ============================ launch ============================
extern "C" void kernel_launch(void* const* d_in, const int* in_sizes, int n_in,
                              void* d_out, int out_size) {
    const float* features = (const float*)d_in[0];
    const int*   src      = (const int*)d_in[1];
    const int*   dst      = (const int*)d_in[2];
    const float* W_self1  = (const float*)d_in[3];
    const float* W_neigh1 = (const float*)d_in[4];
    const float* b1       = (const float*)d_in[5];
    const float* gamma1   = (const float*)d_in[6];
    const float* beta1    = (const float*)d_in[7];
    const float* W_self2  = (const float*)d_in[8];
    const float* W_neigh2 = (const float*)d_in[9];
    const float* b2       = (const float*)d_in[10];
    const float* gamma2   = (const float*)d_in[11];
    const float* beta2    = (const float*)d_in[12];
    float* out = (float*)d_out;

    const int M = in_sizes[0] / IN_F;
    const int E = in_sizes[1];

    void *p_deg, *p_agg, *p_h1, *p_b1hi, *p_b1lo, *p_b2hi, *p_b2lo;
    cudaGetSymbolAddress(&p_deg, g_deg_i);
    cudaGetSymbolAddress(&p_agg, g_agg);
    cudaGetSymbolAddress(&p_h1, g_h1);
    cudaGetSymbolAddress(&p_b1hi, g_B1hi);
    cudaGetSymbolAddress(&p_b1lo, g_B1lo);
    cudaGetSymbolAddress(&p_b2hi, g_B2hi);
    cudaGetSymbolAddress(&p_b2lo, g_B2lo);
    float* agg = (float*)p_agg;
    float* h1  = (float*)p_h1;

    const int eb = (E + 255) / 256;
    const int gatherBlocks = (M + 7) / 8;
    const int ntiles = (M + 127) / 128;
    const int gemmGrid = ntiles < 148 ? ntiles : 148;

    const int stageBytes = 2 * STAGE_WORDS * 4;                 // 66560
    const int smem1 = 8 * HID_F * 128 + stageBytes + 1024;     // 198656
    const int smem2 = 8 * OUT_F * 128 + stageBytes + 1024;     // 133120
    cudaFuncSetAttribute(gemm_tc<HID_F, false>,
                         cudaFuncAttributeMaxDynamicSharedMemorySize, smem1);
    cudaFuncSetAttribute(gemm_tc<OUT_F, true>,
                         cudaFuncAttributeMaxDynamicSharedMemorySize, smem2);

    // CSR build (+ fused weight split & stat zero)
    cudaMemsetAsync(p_deg, 0, (size_t)(N_NODES + 1) * sizeof(int), 0);
    hist_kernel<<<eb, 256>>>(dst, E);
    alloc_kernel<<<(M + 255) / 256, 256>>>(M, W_self1, W_neigh1, W_self2, W_neigh2);
    fill_kernel<<<eb, 256>>>(src, dst, E);

    // ---- layer 1 ----
    gather_kernel<false><<<gatherBlocks, 256>>>(features, M);
    gemm_tc<HID_F, false><<<gemmGrid, 512, smem1>>>(features, agg,
        (const __nv_bfloat16*)p_b1hi, (const __nv_bfloat16*)p_b1lo, b1, h1, M, ntiles);
    bnprep_kernel<HID_F, 1><<<1, HID_F>>>(gamma1, beta1, M);

    // ---- layer 2 ----
    gather_kernel<true><<<gatherBlocks, 256>>>(h1, M);
    gemm_tc<OUT_F, true><<<gemmGrid, 512, smem2>>>(h1, agg,
        (const __nv_bfloat16*)p_b2hi, (const __nv_bfloat16*)p_b2lo, b2, out, M, ntiles);
    bnprep_kernel<OUT_F, 2><<<1, OUT_F>>>(gamma2, beta2, M);
    apply_out_kernel<<<2048, 256>>>(out, (long)M * OUT_F);
}

// round 16
// speedup vs baseline: 1.3507x; 1.0043x over previous
#include <cuda_runtime.h>
#include <cuda_bf16.h>
#include <cstdint>

#define N_NODES 100000
#define N_EDGES 1600000
#define IN_F 128
#define HID_F 128
#define OUT_F 64
#define EPS 1e-5f

#if defined(__CUDA_ARCH_FEAT_SM103_ALL) || defined(__CUDA_ARCH_FEAT_SM100_ALL) || defined(__CUDA_ARCH_FEAT_SM101_ALL)
#define HAS_TCGEN05 1
#else
#define HAS_TCGEN05 0
#endif

// ============================ PTX helpers (sm_103a) ============================
__device__ __forceinline__ uint32_t elect_one() {
    uint32_t pred;
    asm volatile("{\n\t.reg .pred p;\n\telect.sync _|p, 0xFFFFFFFF;\n\tselp.b32 %0, 1, 0, p;\n\t}"
                 : "=r"(pred));
    return pred;
}
__device__ __forceinline__ uint32_t smem_u32(const void* p) {
    uint32_t a;
    asm("{ .reg .u64 t; cvta.to.shared.u64 t, %1; cvt.u32.u64 %0, t; }" : "=r"(a) : "l"(p));
    return a;
}
#define SW128(off) ((off) ^ (((off) >> 3) & 0x70))

static constexpr uint64_t DESC_BASE_SW128 =
    (uint64_t(2) << 61) | (uint64_t(1) << 46) | (uint64_t(64) << 32) | (uint64_t(1) << 16);
__device__ __forceinline__ uint64_t make_desc(uint32_t addr) {
    return DESC_BASE_SW128 | ((uint64_t)(addr >> 4) & 0x3FFF);
}

#if HAS_TCGEN05
#define TC_ALLOC(smem_addr, n) \
    asm volatile("tcgen05.alloc.cta_group::1.sync.aligned.shared::cta.b32 [%0], %1;" \
                 :: "r"(smem_addr), "r"((uint32_t)(n)) : "memory")
#define TC_DEALLOC(tmem, n) \
    asm volatile("tcgen05.dealloc.cta_group::1.sync.aligned.b32 %0, %1;" :: "r"(tmem), "r"((uint32_t)(n)))
#define TC_RELINQ() asm volatile("tcgen05.relinquish_alloc_permit.cta_group::1.sync.aligned;")
#define TC_COMMIT(mbar) \
    asm volatile("tcgen05.commit.cta_group::1.mbarrier::arrive::one.shared::cluster.b64 [%0];" \
                 :: "r"(mbar) : "memory")
#define TC_FENCE_BEFORE() asm volatile("tcgen05.fence::before_thread_sync;" ::: "memory")
#define TC_FENCE_AFTER()  asm volatile("tcgen05.fence::after_thread_sync;" ::: "memory")
#define TC_WAIT_ST()      asm volatile("tcgen05.wait::st.sync.aligned;" ::: "memory")
#define TC_WAIT_LD()      asm volatile("tcgen05.wait::ld.sync.aligned;" ::: "memory")
#define FENCE_ASYNC()     asm volatile("fence.proxy.async.shared::cta;" ::: "memory")
#define MBAR_INIT(a, c) \
    asm volatile("mbarrier.init.shared.b64 [%0], %1;" :: "r"(a), "r"((uint32_t)(c)) : "memory")
#define MBAR_INVAL(a) asm volatile("mbarrier.inval.shared.b64 [%0];" :: "r"(a) : "memory")
#define MBAR_WAIT(mbar, parity) do {                                              \
    uint32_t _m = (mbar), _p = (parity), _done;                                   \
    asm volatile("{\n\t.reg .pred p;\n\t"                                         \
        "mbarrier.try_wait.parity.acquire.cta.shared::cta.b64 p, [%1], %2;\n\t"   \
        "selp.b32 %0, 1, 0, p;\n\t}" : "=r"(_done) : "r"(_m), "r"(_p) : "memory");\
    if (!_done) {                                                                 \
        asm volatile("{\n\t.reg .pred P1;\n\t"                                    \
            "WL_%=:\n\t"                                                          \
            "mbarrier.try_wait.parity.acquire.cta.shared::cta.b64 P1, [%0], %1, 0x989680;\n\t" \
            "@P1 bra.uni WD_%=;\n\tbra.uni WL_%=;\n\tWD_%=:\n\t}"                 \
            :: "r"(_m), "r"(_p) : "memory");                                      \
    } } while (0)

#define TC_ST_X16(addr, r) \
    asm volatile( \
        "tcgen05.st.sync.aligned.32x32b.x16.b32 [%0], " \
        "{%1, %2, %3, %4, %5, %6, %7, %8, %9, %10, %11, %12, %13, %14, %15, %16};" \
        :: "r"(addr), \
           "r"((r)[0]),  "r"((r)[1]),  "r"((r)[2]),  "r"((r)[3]), \
           "r"((r)[4]),  "r"((r)[5]),  "r"((r)[6]),  "r"((r)[7]), \
           "r"((r)[8]),  "r"((r)[9]),  "r"((r)[10]), "r"((r)[11]), \
           "r"((r)[12]), "r"((r)[13]), "r"((r)[14]), "r"((r)[15]) \
        : "memory")

#define TC_LD_X32(r, addr) \
    asm volatile( \
        "tcgen05.ld.sync.aligned.32x32b.x32.b32 " \
        "{%0, %1, %2, %3, %4, %5, %6, %7, %8, %9, %10, %11, %12, %13, %14, %15, " \
        " %16, %17, %18, %19, %20, %21, %22, %23, %24, %25, %26, %27, %28, %29, %30, %31}, [%32];" \
        : "=r"((r)[0]),  "=r"((r)[1]),  "=r"((r)[2]),  "=r"((r)[3]), \
          "=r"((r)[4]),  "=r"((r)[5]),  "=r"((r)[6]),  "=r"((r)[7]), \
          "=r"((r)[8]),  "=r"((r)[9]),  "=r"((r)[10]), "=r"((r)[11]), \
          "=r"((r)[12]), "=r"((r)[13]), "=r"((r)[14]), "=r"((r)[15]), \
          "=r"((r)[16]), "=r"((r)[17]), "=r"((r)[18]), "=r"((r)[19]), \
          "=r"((r)[20]), "=r"((r)[21]), "=r"((r)[22]), "=r"((r)[23]), \
          "=r"((r)[24]), "=r"((r)[25]), "=r"((r)[26]), "=r"((r)[27]), \
          "=r"((r)[28]), "=r"((r)[29]), "=r"((r)[30]), "=r"((r)[31]) \
        : "r"(addr))

__device__ __forceinline__ void mma_f16_ts(uint32_t d_tmem, uint32_t a_tmem, uint64_t b_desc,
                                           uint32_t idesc, bool en) {
    uint32_t e = en ? 1u : 0u;
    asm volatile(
        "{\n\t.reg .pred p;\n\tsetp.ne.u32 p, %5, 0;\n\t"
        "tcgen05.mma.cta_group::1.kind::f16 [%0], [%1], %2, %3, {%4, %4, %4, %4}, p;\n\t}"
        :: "r"(d_tmem), "r"(a_tmem), "l"(b_desc), "r"(idesc), "r"(0u), "r"(e) : "memory");
}
#endif // HAS_TCGEN05

// ============================ scratch ============================
__device__ __align__(16) float g_agg[(size_t)N_NODES * HID_F];
__device__ __align__(16) float g_h1 [(size_t)N_NODES * HID_F];
__device__ int   g_deg_i[N_NODES + 1];    // [N_NODES] = allocation counter
__device__ int   g_rowstart[N_NODES];
__device__ int   g_cursor[N_NODES];
__device__ int   g_csr_src[N_EDGES];
__device__ float g_fsum[HID_F];
__device__ float g_fsumsq[HID_F];
__device__ __align__(16) float g_scale1[HID_F];
__device__ __align__(16) float g_shift1[HID_F];
__device__ __align__(16) float g_scale2[OUT_F];
__device__ __align__(16) float g_shift2[OUT_F];
__device__ __nv_bfloat16 g_B1hi[128 * 256];
__device__ __nv_bfloat16 g_B1lo[128 * 256];
__device__ __nv_bfloat16 g_B2hi[64 * 256];
__device__ __nv_bfloat16 g_B2lo[64 * 256];

// ============================ CSR build ============================
__global__ void hist_kernel(const int* __restrict__ dst, int E) {
    int e = blockIdx.x * blockDim.x + threadIdx.x;
    if (e < E) atomicAdd(&g_deg_i[dst[e]], 1);
}
// slot allocation + BN-stat zero + weight split (fused)
__global__ void alloc_kernel(int M,
                             const float* __restrict__ Ws1, const float* __restrict__ Wn1,
                             const float* __restrict__ Ws2, const float* __restrict__ Wn2) {
    int i = blockIdx.x * blockDim.x + threadIdx.x;
    if (i < M) {
        int d = g_deg_i[i];
        int s = atomicAdd(&g_deg_i[N_NODES], d);
        g_rowstart[i] = s;
        g_cursor[i]   = s;
    }
    if (blockIdx.x == 0 && threadIdx.x < HID_F) {
        g_fsum[threadIdx.x] = 0.f;
        g_fsumsq[threadIdx.x] = 0.f;
    }
    const int n1 = 128 * 256;
    if (i < n1) {
        int n = i >> 8, k = i & 255;
        float w = (k < 128) ? Ws1[(size_t)k * 128 + n] : Wn1[(size_t)(k - 128) * 128 + n];
        __nv_bfloat16 h = __float2bfloat16(w);
        g_B1hi[(size_t)n * 256 + k] = h;
        g_B1lo[(size_t)n * 256 + k] = __float2bfloat16(w - __bfloat162float(h));
    } else if (i < n1 + 64 * 256) {
        int j = i - n1;
        int n = j >> 8, k = j & 255;
        float w = (k < 128) ? Ws2[(size_t)k * 64 + n] : Wn2[(size_t)(k - 128) * 64 + n];
        __nv_bfloat16 h = __float2bfloat16(w);
        g_B2hi[(size_t)n * 256 + k] = h;
        g_B2lo[(size_t)n * 256 + k] = __float2bfloat16(w - __bfloat162float(h));
    }
}
__global__ void fill_kernel(const int* __restrict__ src, const int* __restrict__ dst, int E) {
    int e = blockIdx.x * blockDim.x + threadIdx.x;
    if (e < E) {
        int slot = atomicAdd(&g_cursor[dst[e]], 1);
        g_csr_src[slot] = src[e];
    }
}

// ============================ gather aggregation (warp per node) ============================
__device__ __forceinline__ void bn_relu4(float4& v, const float4& sc, const float4& sh) {
    v.x = fmaxf(fmaf(v.x, sc.x, sh.x), 0.0f);
    v.y = fmaxf(fmaf(v.y, sc.y, sh.y), 0.0f);
    v.z = fmaxf(fmaf(v.z, sc.z, sh.z), 0.0f);
    v.w = fmaxf(fmaf(v.w, sc.w, sh.w), 0.0f);
}
template <bool BN>
__global__ void __launch_bounds__(256)
gather_kernel(const float* __restrict__ h, int M) {
    int node = blockIdx.x * 8 + (threadIdx.x >> 5);
    int lane = threadIdx.x & 31;
    if (node >= M) return;
    int beg = g_rowstart[node];
    int cnt = g_deg_i[node];
    float4 acc = make_float4(0.f, 0.f, 0.f, 0.f);
    float4 sc, sh;
    if (BN) {
        sc = *(const float4*)(g_scale1 + lane * 4);
        sh = *(const float4*)(g_shift1 + lane * 4);
    }
    for (int j0 = 0; j0 < cnt; j0 += 32) {
        int rem = cnt - j0;
        int lim = rem < 32 ? rem : 32;
        int myidx = (lane < lim) ? __ldg(&g_csr_src[beg + j0 + lane]) : 0;
        int jj = 0;
        for (; jj + 4 <= lim; jj += 4) {
            int s0 = __shfl_sync(0xffffffffu, myidx, jj);
            int s1 = __shfl_sync(0xffffffffu, myidx, jj + 1);
            int s2 = __shfl_sync(0xffffffffu, myidx, jj + 2);
            int s3 = __shfl_sync(0xffffffffu, myidx, jj + 3);
            float4 v0 = __ldg((const float4*)(h + (size_t)s0 * 128) + lane);
            float4 v1 = __ldg((const float4*)(h + (size_t)s1 * 128) + lane);
            float4 v2 = __ldg((const float4*)(h + (size_t)s2 * 128) + lane);
            float4 v3 = __ldg((const float4*)(h + (size_t)s3 * 128) + lane);
            if (BN) { bn_relu4(v0, sc, sh); bn_relu4(v1, sc, sh); bn_relu4(v2, sc, sh); bn_relu4(v3, sc, sh); }
            acc.x += (v0.x + v1.x) + (v2.x + v3.x);
            acc.y += (v0.y + v1.y) + (v2.y + v3.y);
            acc.z += (v0.z + v1.z) + (v2.z + v3.z);
            acc.w += (v0.w + v1.w) + (v2.w + v3.w);
        }
        for (; jj < lim; ++jj) {
            int s0 = __shfl_sync(0xffffffffu, myidx, jj);
            float4 v0 = __ldg((const float4*)(h + (size_t)s0 * 128) + lane);
            if (BN) bn_relu4(v0, sc, sh);
            acc.x += v0.x; acc.y += v0.y; acc.z += v0.z; acc.w += v0.w;
        }
    }
    float r = 1.0f / (float)(cnt > 0 ? cnt : 1);
    acc.x *= r; acc.y *= r; acc.z *= r; acc.w *= r;
    *(float4*)(g_agg + (size_t)node * 128 + lane * 4) = acc;
}

// ============================ persistent pipelined tcgen05 TS GEMM ============================
// C[M,NOUT] = A'[M,128] @ Wself + agg[M,128] @ Wneigh + bias ; A' = BNIN ? relu(bn(A)) : A
// Persistent 148 CTAs; B loaded once; TMEM alloc'd once; per-tile parity-alternating commit.
// D double-buffered in TMEM: epilogue(t-1) reads D[prev] while MMA(t) writes D[cur],
// so the epilogue is fully off the wait→tmemst critical chain.
// TMEM: A-hi [0,128), A-lo [128,256), D0 at 256, D1 at 256+NOUT.
#define STAGE_WORDS (128 * 65)
template <int NOUT, bool BNIN>
__global__ void __launch_bounds__(512) __cluster_dims__(1, 1, 1)
gemm_tc(const float* __restrict__ A, const float* __restrict__ Aneigh,
        const __nv_bfloat16* __restrict__ Bhi, const __nv_bfloat16* __restrict__ Blo,
        const float* __restrict__ bias, float* __restrict__ C, int M, int ntiles) {
#if HAS_TCGEN05
    extern __shared__ unsigned char smem_raw[];
    __shared__ uint32_t s_tmem[1];
    __shared__ __align__(8) unsigned long long s_mbar[1];

    const int tid = threadIdx.x;
    const int wid = tid >> 5;
    const int lane = tid & 31;
    constexpr int BBYTES = 8 * NOUT * 128;

    unsigned char* sB = (unsigned char*)(((uintptr_t)smem_raw + 1023) & ~(uintptr_t)1023);
    uint32_t* hiTile = (uint32_t*)(sB + BBYTES);
    uint32_t* loTile = hiTile + STAGE_WORDS;
    const uint32_t sB_addr = smem_u32(sB);
    const uint32_t tptr_addr = smem_u32(s_tmem);
    const uint32_t mbar_addr = smem_u32(s_mbar);
    const uint32_t warp_off = (uint32_t)(wid & 3) << 21;

    if (tid == 0) MBAR_INIT(mbar_addr, 1);

    // ---- B load ONCE ----
    for (int idx = tid; idx < 8 * NOUT * 8; idx += 512) {
        int c = idx / (NOUT * 8);
        int rem = idx - c * (NOUT * 8);
        int n = rem >> 3;
        int q = rem & 7;
        const __nv_bfloat16* s = ((q & 4) ? Blo : Bhi) + (size_t)n * 256 + c * 32 + (q & 3) * 8;
        uint4 val = *(const uint4*)s;
        uint32_t off = (uint32_t)(n * 128 + ((q & 4) ? 64 : 0) + (q & 3) * 16);
        *(uint4*)(sB + c * (NOUT * 128) + SW128(off)) = val;
    }

    if (wid == 0) TC_ALLOC(tptr_addr, 512);
    __syncthreads();
    if (wid == 0) TC_RELINQ();
    uint32_t tmem;
    asm volatile("ld.shared.b32 %0, [%1];" : "=r"(tmem) : "r"(tptr_addr));
    FENCE_ASYNC();
    __syncthreads();

    constexpr uint32_t IDESC =
        (1u << 4) | (1u << 7) | (1u << 10) | ((uint32_t)(NOUT / 8) << 17) | (8u << 24);
    const int myrow = tid & 127;
    const int sub = tid >> 7;
    int ph = 0;

    auto stage = [&](int row0, int p) {
        const float* __restrict__ srcM = p ? Aneigh : A;
        #pragma unroll
        for (int it = 0; it < 8; ++it) {
            int idx = tid + it * 512;
            int r = idx >> 5;
            int q = idx & 31;
            int gr = row0 + r;
            float4 v = make_float4(0.f, 0.f, 0.f, 0.f);
            if (gr < M) {
                v = *(const float4*)(srcM + (size_t)gr * 128 + q * 4);
                if (BNIN && p == 0) {
                    float4 sc = *(const float4*)(g_scale1 + q * 4);
                    float4 sh = *(const float4*)(g_shift1 + q * 4);
                    bn_relu4(v, sc, sh);
                }
            }
            uint32_t ux = __float_as_uint(v.x), uy = __float_as_uint(v.y);
            uint32_t uz = __float_as_uint(v.z), uw = __float_as_uint(v.w);
            uint32_t hi0 = __byte_perm(ux, uy, 0x7632);
            uint32_t hi1 = __byte_perm(uz, uw, 0x7632);
            float lx = v.x - __uint_as_float(ux & 0xFFFF0000u);
            float ly = v.y - __uint_as_float(uy & 0xFFFF0000u);
            float lz = v.z - __uint_as_float(uz & 0xFFFF0000u);
            float lw = v.w - __uint_as_float(uw & 0xFFFF0000u);
            uint32_t lo0 = __byte_perm(__float_as_uint(lx), __float_as_uint(ly), 0x7632);
            uint32_t lo1 = __byte_perm(__float_as_uint(lz), __float_as_uint(lw), 0x7632);
            int base = r * 65 + q * 2;
            hiTile[base] = hi0; hiTile[base + 1] = hi1;
            loTile[base] = lo0; loTile[base + 1] = lo1;
        }
    };
    auto tmemst = [&](int p) {
        uint32_t hr[16], lr[16];
        int base = myrow * 65 + sub * 16;
        #pragma unroll
        for (int i = 0; i < 16; ++i) { hr[i] = hiTile[base + i]; lr[i] = loTile[base + i]; }
        uint32_t col = (uint32_t)(p * 64 + sub * 16);
        TC_ST_X16(tmem + col + warp_off, hr);
        TC_ST_X16(tmem + 128 + col + warp_off, lr);
    };
    auto epilogue = [&](int row0, uint32_t d_tmem) {
        const int cset = wid >> 2;
        if (cset >= NOUT / 32) return;
        const int cbase = cset * 32;
        const int row = row0 + (wid & 3) * 32 + lane;
        const bool valid = (row < M);
        uint32_t dr[32];
        TC_LD_X32(dr, d_tmem + cbase);
        TC_WAIT_LD();
        float s[32], q[32];
        #pragma unroll
        for (int j = 0; j < 32; ++j) {
            float y = __uint_as_float(dr[j]) + __ldg(&bias[cbase + j]);
            s[j] = valid ? y : 0.f;
            q[j] = valid ? y * y : 0.f;
            dr[j] = __float_as_uint(y);
        }
        if (valid) {
            #pragma unroll
            for (int j = 0; j < 32; j += 4)
                *(float4*)(C + (size_t)row * NOUT + cbase + j) =
                    make_float4(__uint_as_float(dr[j]), __uint_as_float(dr[j + 1]),
                                __uint_as_float(dr[j + 2]), __uint_as_float(dr[j + 3]));
        }
        #pragma unroll
        for (int half = 16; half >= 1; half >>= 1) {
            bool up = (lane & half) != 0;
            #pragma unroll
            for (int j = 0; j < half; ++j) {
                float ssend = up ? s[j] : s[j + half];
                float qsend = up ? q[j] : q[j + half];
                float srecv = __shfl_xor_sync(0xffffffffu, ssend, half);
                float qrecv = __shfl_xor_sync(0xffffffffu, qsend, half);
                s[j] = (up ? s[j + half] : s[j]) + srecv;
                q[j] = (up ? q[j + half] : q[j]) + qrecv;
            }
        }
        atomicAdd(&g_fsum[cbase + lane], s[0]);
        atomicAdd(&g_fsumsq[cbase + lane], q[0]);
    };

    int tile = blockIdx.x;
    int pend_row0 = 0;
    int pendbuf = 0;
    int curbuf = 0;
    bool have_pending = false;
    if (tile < ntiles) stage(tile * 128, 0);
    __syncthreads();

    while (tile < ntiles) {
        const int row0 = tile * 128;
        // A columns are MMA input: wait for the in-flight MMA before overwriting
        if (have_pending) {
            MBAR_WAIT(mbar_addr, ph);
            ph ^= 1;
            TC_FENCE_AFTER();
        }
        __syncthreads();
        tmemst(0);
        __syncthreads();
        stage(row0, 1);
        __syncthreads();
        tmemst(1);
        TC_WAIT_ST();
        TC_FENCE_BEFORE();
        __syncthreads();
        const uint32_t d_cur = tmem + 256 + (uint32_t)curbuf * NOUT;
        if (wid == 0) {
            TC_FENCE_AFTER();
            if (elect_one()) {
                #pragma unroll
                for (int t = 0; t < 16; ++t) {
                    int c = t >> 1, ss = t & 1;
                    uint64_t dhi = make_desc(sB_addr + c * (NOUT * 128)) + 2 * ss;
                    uint64_t dlo = dhi + 4;
                    mma_f16_ts(d_cur, tmem + t * 8,       dhi, IDESC, t > 0);
                    mma_f16_ts(d_cur, tmem + t * 8,       dlo, IDESC, true);
                    mma_f16_ts(d_cur, tmem + 128 + t * 8, dhi, IDESC, true);
                }
                TC_COMMIT(mbar_addr);
            }
        }
        // overlap with the MMA just committed: previous tile's epilogue + next tile's stage
        if (have_pending) epilogue(pend_row0, tmem + 256 + (uint32_t)pendbuf * NOUT);
        pend_row0 = row0;
        pendbuf = curbuf;
        curbuf ^= 1;
        have_pending = true;
        tile += gridDim.x;
        if (tile < ntiles) stage(tile * 128, 0);
        __syncthreads();
    }
    if (have_pending) {
        MBAR_WAIT(mbar_addr, ph);
        ph ^= 1;
        TC_FENCE_AFTER();
        epilogue(pend_row0, tmem + 256 + (uint32_t)pendbuf * NOUT);
    }
    __syncthreads();
    if (tid == 0) MBAR_INVAL(mbar_addr);
    if (wid == 0) TC_DEALLOC(tmem, 512);
#else
    // SIMT fallback (plain compute_103 PTX pass; never selected at runtime)
    const int tid = threadIdx.x;
    for (int tile = blockIdx.x; tile < ntiles; tile += gridDim.x) {
        const int row = tile * 128 + (tid & 127);
        if (tid < 128 && row < M) {
            float acc[NOUT];
            #pragma unroll
            for (int n = 0; n < NOUT; ++n) acc[n] = 0.f;
            for (int k = 0; k < 256; ++k) {
                float a;
                if (k < 128) {
                    a = A[(size_t)row * 128 + k];
                    if (BNIN) a = fmaxf(fmaf(a, g_scale1[k], g_shift1[k]), 0.f);
                } else {
                    a = Aneigh[(size_t)row * 128 + (k - 128)];
                }
                for (int n = 0; n < NOUT; ++n) {
                    float w = __bfloat162float(Bhi[(size_t)n * 256 + k]) +
                              __bfloat162float(Blo[(size_t)n * 256 + k]);
                    acc[n] += a * w;
                }
            }
            for (int n = 0; n < NOUT; ++n) {
                float y = acc[n] + bias[n];
                C[(size_t)row * NOUT + n] = y;
                atomicAdd(&g_fsum[n], y);
                atomicAdd(&g_fsumsq[n], y * y);
            }
        }
    }
#endif
}

// ============================ BN prep (zeroes stats after reading) ============================
template <int COLS, int LAYER>
__global__ void bnprep_kernel(const float* __restrict__ gamma,
                              const float* __restrict__ beta, int M) {
    int c = threadIdx.x;
    if (c >= COLS) return;
    float invM = 1.0f / (float)M;
    float mu = g_fsum[c] * invM;
    float var = g_fsumsq[c] * invM - mu * mu;
    if (var < 0.f) var = 0.f;
    float sc = gamma[c] * rsqrtf(var + EPS);
    if (LAYER == 1) { g_scale1[c] = sc; g_shift1[c] = beta[c] - mu * sc; }
    else            { g_scale2[c] = sc; g_shift2[c] = beta[c] - mu * sc; }
    g_fsum[c] = 0.f;
    g_fsumsq[c] = 0.f;
}
__global__ void apply_out_kernel(float* __restrict__ h, long total) {
    long i = ((long)blockIdx.x * blockDim.x + threadIdx.x) * 4;
    long stride = (long)gridDim.x * blockDim.x * 4;
    for (; i < total; i += stride) {
        int c = (int)(i & (OUT_F - 1));
        float4 v = *(float4*)(h + i);
        float4 sc = *(const float4*)(g_scale2 + c);
        float4 sh = *(const float4*)(g_shift2 + c);
        v.x = fmaf(v.x, sc.x, sh.x);
        v.y = fmaf(v.y, sc.y, sh.y);
        v.z = fmaf(v.z, sc.z, sh.z);
        v.w = fmaf(v.w, sc.w, sh.w);
        *(float4*)(h + i) = v;
    }
}

// ============================ launch ============================
extern "C" void kernel_launch(void* const* d_in, const int* in_sizes, int n_in,
                              void* d_out, int out_size) {
    const float* features = (const float*)d_in[0];
    const int*   src      = (const int*)d_in[1];
    const int*   dst      = (const int*)d_in[2];
    const float* W_self1  = (const float*)d_in[3];
    const float* W_neigh1 = (const float*)d_in[4];
    const float* b1       = (const float*)d_in[5];
    const float* gamma1   = (const float*)d_in[6];
    const float* beta1    = (const float*)d_in[7];
    const float* W_self2  = (const float*)d_in[8];
    const float* W_neigh2 = (const float*)d_in[9];
    const float* b2       = (const float*)d_in[10];
    const float* gamma2   = (const float*)d_in[11];
    const float* beta2    = (const float*)d_in[12];
    float* out = (float*)d_out;

    const int M = in_sizes[0] / IN_F;
    const int E = in_sizes[1];

    void *p_deg, *p_agg, *p_h1, *p_b1hi, *p_b1lo, *p_b2hi, *p_b2lo;
    cudaGetSymbolAddress(&p_deg, g_deg_i);
    cudaGetSymbolAddress(&p_agg, g_agg);
    cudaGetSymbolAddress(&p_h1, g_h1);
    cudaGetSymbolAddress(&p_b1hi, g_B1hi);
    cudaGetSymbolAddress(&p_b1lo, g_B1lo);
    cudaGetSymbolAddress(&p_b2hi, g_B2hi);
    cudaGetSymbolAddress(&p_b2lo, g_B2lo);
    float* agg = (float*)p_agg;
    float* h1  = (float*)p_h1;

    const int eb = (E + 255) / 256;
    const int gatherBlocks = (M + 7) / 8;
    const int ntiles = (M + 127) / 128;
    const int gemmGrid = ntiles < 148 ? ntiles : 148;

    const int stageBytes = 2 * STAGE_WORDS * 4;                 // 66560
    const int smem1 = 8 * HID_F * 128 + stageBytes + 1024;     // 198656
    const int smem2 = 8 * OUT_F * 128 + stageBytes + 1024;     // 133120
    cudaFuncSetAttribute(gemm_tc<HID_F, false>,
                         cudaFuncAttributeMaxDynamicSharedMemorySize, smem1);
    cudaFuncSetAttribute(gemm_tc<OUT_F, true>,
                         cudaFuncAttributeMaxDynamicSharedMemorySize, smem2);

    // CSR build (+ fused weight split & stat zero)
    cudaMemsetAsync(p_deg, 0, (size_t)(N_NODES + 1) * sizeof(int), 0);
    hist_kernel<<<eb, 256>>>(dst, E);
    alloc_kernel<<<(M + 255) / 256, 256>>>(M, W_self1, W_neigh1, W_self2, W_neigh2);
    fill_kernel<<<eb, 256>>>(src, dst, E);

    // ---- layer 1 ----
    gather_kernel<false><<<gatherBlocks, 256>>>(features, M);
    gemm_tc<HID_F, false><<<gemmGrid, 512, smem1>>>(features, agg,
        (const __nv_bfloat16*)p_b1hi, (const __nv_bfloat16*)p_b1lo, b1, h1, M, ntiles);
    bnprep_kernel<HID_F, 1><<<1, HID_F>>>(gamma1, beta1, M);

    // ---- layer 2 ----
    gather_kernel<true><<<gatherBlocks, 256>>>(h1, M);
    gemm_tc<OUT_F, true><<<gemmGrid, 512, smem2>>>(h1, agg,
        (const __nv_bfloat16*)p_b2hi, (const __nv_bfloat16*)p_b2lo, b2, out, M, ntiles);
    bnprep_kernel<OUT_F, 2><<<1, OUT_F>>>(gamma2, beta2, M);
    apply_out_kernel<<<2048, 256>>>(out, (long)M * OUT_F);
}

// round 17
// speedup vs baseline: 1.5581x; 1.1536x over previous
#include <cuda_runtime.h>
#include <cuda_bf16.h>
#include <cstdint>

#define N_NODES 100000
#define N_EDGES 1600000
#define IN_F 128
#define HID_F 128
#define OUT_F 64
#define EPS 1e-5f

#if defined(__CUDA_ARCH_FEAT_SM103_ALL) || defined(__CUDA_ARCH_FEAT_SM100_ALL) || defined(__CUDA_ARCH_FEAT_SM101_ALL)
#define HAS_TCGEN05 1
#else
#define HAS_TCGEN05 0
#endif

// ============================ PTX helpers (sm_103a) ============================
__device__ __forceinline__ uint32_t elect_one() {
    uint32_t pred;
    asm volatile("{\n\t.reg .pred p;\n\telect.sync _|p, 0xFFFFFFFF;\n\tselp.b32 %0, 1, 0, p;\n\t}"
                 : "=r"(pred));
    return pred;
}
__device__ __forceinline__ uint32_t smem_u32(const void* p) {
    uint32_t a;
    asm("{ .reg .u64 t; cvta.to.shared.u64 t, %1; cvt.u32.u64 %0, t; }" : "=r"(a) : "l"(p));
    return a;
}
#define SW128(off) ((off) ^ (((off) >> 3) & 0x70))

static constexpr uint64_t DESC_BASE_SW128 =
    (uint64_t(2) << 61) | (uint64_t(1) << 46) | (uint64_t(64) << 32) | (uint64_t(1) << 16);
__device__ __forceinline__ uint64_t make_desc(uint32_t addr) {
    return DESC_BASE_SW128 | ((uint64_t)(addr >> 4) & 0x3FFF);
}

#if HAS_TCGEN05
#define TC_ALLOC(smem_addr, n) \
    asm volatile("tcgen05.alloc.cta_group::1.sync.aligned.shared::cta.b32 [%0], %1;" \
                 :: "r"(smem_addr), "r"((uint32_t)(n)) : "memory")
#define TC_DEALLOC(tmem, n) \
    asm volatile("tcgen05.dealloc.cta_group::1.sync.aligned.b32 %0, %1;" :: "r"(tmem), "r"((uint32_t)(n)))
#define TC_RELINQ() asm volatile("tcgen05.relinquish_alloc_permit.cta_group::1.sync.aligned;")
#define TC_COMMIT(mbar) \
    asm volatile("tcgen05.commit.cta_group::1.mbarrier::arrive::one.shared::cluster.b64 [%0];" \
                 :: "r"(mbar) : "memory")
#define TC_FENCE_BEFORE() asm volatile("tcgen05.fence::before_thread_sync;" ::: "memory")
#define TC_FENCE_AFTER()  asm volatile("tcgen05.fence::after_thread_sync;" ::: "memory")
#define TC_WAIT_ST()      asm volatile("tcgen05.wait::st.sync.aligned;" ::: "memory")
#define TC_WAIT_LD()      asm volatile("tcgen05.wait::ld.sync.aligned;" ::: "memory")
#define FENCE_ASYNC()     asm volatile("fence.proxy.async.shared::cta;" ::: "memory")
#define MBAR_INIT(a, c) \
    asm volatile("mbarrier.init.shared.b64 [%0], %1;" :: "r"(a), "r"((uint32_t)(c)) : "memory")
#define MBAR_INVAL(a) asm volatile("mbarrier.inval.shared.b64 [%0];" :: "r"(a) : "memory")
#define MBAR_WAIT(mbar, parity) do {                                              \
    uint32_t _m = (mbar), _p = (parity), _done;                                   \
    asm volatile("{\n\t.reg .pred p;\n\t"                                         \
        "mbarrier.try_wait.parity.acquire.cta.shared::cta.b64 p, [%1], %2;\n\t"   \
        "selp.b32 %0, 1, 0, p;\n\t}" : "=r"(_done) : "r"(_m), "r"(_p) : "memory");\
    if (!_done) {                                                                 \
        asm volatile("{\n\t.reg .pred P1;\n\t"                                    \
            "WL_%=:\n\t"                                                          \
            "mbarrier.try_wait.parity.acquire.cta.shared::cta.b64 P1, [%0], %1, 0x989680;\n\t" \
            "@P1 bra.uni WD_%=;\n\tbra.uni WL_%=;\n\tWD_%=:\n\t}"                 \
            :: "r"(_m), "r"(_p) : "memory");                                      \
    } } while (0)

#define TC_ST_X16(addr, r) \
    asm volatile( \
        "tcgen05.st.sync.aligned.32x32b.x16.b32 [%0], " \
        "{%1, %2, %3, %4, %5, %6, %7, %8, %9, %10, %11, %12, %13, %14, %15, %16};" \
        :: "r"(addr), \
           "r"((r)[0]),  "r"((r)[1]),  "r"((r)[2]),  "r"((r)[3]), \
           "r"((r)[4]),  "r"((r)[5]),  "r"((r)[6]),  "r"((r)[7]), \
           "r"((r)[8]),  "r"((r)[9]),  "r"((r)[10]), "r"((r)[11]), \
           "r"((r)[12]), "r"((r)[13]), "r"((r)[14]), "r"((r)[15]) \
        : "memory")

#define TC_LD_X32(r, addr) \
    asm volatile( \
        "tcgen05.ld.sync.aligned.32x32b.x32.b32 " \
        "{%0, %1, %2, %3, %4, %5, %6, %7, %8, %9, %10, %11, %12, %13, %14, %15, " \
        " %16, %17, %18, %19, %20, %21, %22, %23, %24, %25, %26, %27, %28, %29, %30, %31}, [%32];" \
        : "=r"((r)[0]),  "=r"((r)[1]),  "=r"((r)[2]),  "=r"((r)[3]), \
          "=r"((r)[4]),  "=r"((r)[5]),  "=r"((r)[6]),  "=r"((r)[7]), \
          "=r"((r)[8]),  "=r"((r)[9]),  "=r"((r)[10]), "=r"((r)[11]), \
          "=r"((r)[12]), "=r"((r)[13]), "=r"((r)[14]), "=r"((r)[15]), \
          "=r"((r)[16]), "=r"((r)[17]), "=r"((r)[18]), "=r"((r)[19]), \
          "=r"((r)[20]), "=r"((r)[21]), "=r"((r)[22]), "=r"((r)[23]), \
          "=r"((r)[24]), "=r"((r)[25]), "=r"((r)[26]), "=r"((r)[27]), \
          "=r"((r)[28]), "=r"((r)[29]), "=r"((r)[30]), "=r"((r)[31]) \
        : "r"(addr))

__device__ __forceinline__ void mma_f16_ts(uint32_t d_tmem, uint32_t a_tmem, uint64_t b_desc,
                                           uint32_t idesc, bool en) {
    uint32_t e = en ? 1u : 0u;
    asm volatile(
        "{\n\t.reg .pred p;\n\tsetp.ne.u32 p, %5, 0;\n\t"
        "tcgen05.mma.cta_group::1.kind::f16 [%0], [%1], %2, %3, {%4, %4, %4, %4}, p;\n\t}"
        :: "r"(d_tmem), "r"(a_tmem), "l"(b_desc), "r"(idesc), "r"(0u), "r"(e) : "memory");
}
#endif // HAS_TCGEN05

// ============================ scratch ============================
__device__ __align__(16) float g_agg[(size_t)N_NODES * HID_F];  // L1 agg / L2 [Zs|Zn]
__device__ __align__(16) float g_h1 [(size_t)N_NODES * HID_F];
__device__ int   g_deg_i[N_NODES + 1];    // [N_NODES] = allocation counter
__device__ int   g_rowstart[N_NODES];
__device__ int   g_cursor[N_NODES];
__device__ int   g_csr_src[N_EDGES];
__device__ float g_fsum[HID_F];
__device__ float g_fsumsq[HID_F];
__device__ __align__(16) float g_scale1[HID_F];
__device__ __align__(16) float g_shift1[HID_F];
__device__ __align__(16) float g_scale2[OUT_F];
__device__ __align__(16) float g_shift2[OUT_F];
__device__ __nv_bfloat16 g_B1hi[128 * 256];
__device__ __nv_bfloat16 g_B1lo[128 * 256];
__device__ __nv_bfloat16 g_B2hi[128 * 128];   // [Ws2 | Wn2] along N, K=128, n-major
__device__ __nv_bfloat16 g_B2lo[128 * 128];

// ============================ CSR build ============================
__global__ void hist_kernel(const int* __restrict__ dst, int E) {
    int e = blockIdx.x * blockDim.x + threadIdx.x;
    if (e < E) atomicAdd(&g_deg_i[dst[e]], 1);
}
__global__ void alloc_kernel(int M,
                             const float* __restrict__ Ws1, const float* __restrict__ Wn1,
                             const float* __restrict__ Ws2, const float* __restrict__ Wn2) {
    int i = blockIdx.x * blockDim.x + threadIdx.x;
    if (i < M) {
        int d = g_deg_i[i];
        int s = atomicAdd(&g_deg_i[N_NODES], d);
        g_rowstart[i] = s;
        g_cursor[i]   = s;
    }
    if (blockIdx.x == 0 && threadIdx.x < HID_F) {
        g_fsum[threadIdx.x] = 0.f;
        g_fsumsq[threadIdx.x] = 0.f;
    }
    const int n1 = 128 * 256;
    if (i < n1) {
        int n = i >> 8, k = i & 255;
        float w = (k < 128) ? Ws1[(size_t)k * 128 + n] : Wn1[(size_t)(k - 128) * 128 + n];
        __nv_bfloat16 h = __float2bfloat16(w);
        g_B1hi[(size_t)n * 256 + k] = h;
        g_B1lo[(size_t)n * 256 + k] = __float2bfloat16(w - __bfloat162float(h));
    } else if (i < n1 + 128 * 128) {
        int j = i - n1;
        int n = j >> 7, k = j & 127;
        float w = (n < 64) ? Ws2[(size_t)k * 64 + n] : Wn2[(size_t)k * 64 + (n - 64)];
        __nv_bfloat16 h = __float2bfloat16(w);
        g_B2hi[(size_t)n * 128 + k] = h;
        g_B2lo[(size_t)n * 128 + k] = __float2bfloat16(w - __bfloat162float(h));
    }
}
__global__ void fill_kernel(const int* __restrict__ src, const int* __restrict__ dst, int E) {
    int e = blockIdx.x * blockDim.x + threadIdx.x;
    if (e < E) {
        int slot = atomicAdd(&g_cursor[dst[e]], 1);
        g_csr_src[slot] = src[e];
    }
}

// ============================ layer-1 gather (warp per node, 128 cols) ============================
__device__ __forceinline__ void bn_relu4(float4& v, const float4& sc, const float4& sh) {
    v.x = fmaxf(fmaf(v.x, sc.x, sh.x), 0.0f);
    v.y = fmaxf(fmaf(v.y, sc.y, sh.y), 0.0f);
    v.z = fmaxf(fmaf(v.z, sc.z, sh.z), 0.0f);
    v.w = fmaxf(fmaf(v.w, sc.w, sh.w), 0.0f);
}
__global__ void __launch_bounds__(256)
gather_kernel(const float* __restrict__ h, int M) {
    int node = blockIdx.x * 8 + (threadIdx.x >> 5);
    int lane = threadIdx.x & 31;
    if (node >= M) return;
    int beg = g_rowstart[node];
    int cnt = g_deg_i[node];
    float4 acc = make_float4(0.f, 0.f, 0.f, 0.f);
    for (int j0 = 0; j0 < cnt; j0 += 32) {
        int rem = cnt - j0;
        int lim = rem < 32 ? rem : 32;
        int myidx = (lane < lim) ? __ldg(&g_csr_src[beg + j0 + lane]) : 0;
        int jj = 0;
        for (; jj + 4 <= lim; jj += 4) {
            int s0 = __shfl_sync(0xffffffffu, myidx, jj);
            int s1 = __shfl_sync(0xffffffffu, myidx, jj + 1);
            int s2 = __shfl_sync(0xffffffffu, myidx, jj + 2);
            int s3 = __shfl_sync(0xffffffffu, myidx, jj + 3);
            float4 v0 = __ldg((const float4*)(h + (size_t)s0 * 128) + lane);
            float4 v1 = __ldg((const float4*)(h + (size_t)s1 * 128) + lane);
            float4 v2 = __ldg((const float4*)(h + (size_t)s2 * 128) + lane);
            float4 v3 = __ldg((const float4*)(h + (size_t)s3 * 128) + lane);
            acc.x += (v0.x + v1.x) + (v2.x + v3.x);
            acc.y += (v0.y + v1.y) + (v2.y + v3.y);
            acc.z += (v0.z + v1.z) + (v2.z + v3.z);
            acc.w += (v0.w + v1.w) + (v2.w + v3.w);
        }
        for (; jj < lim; ++jj) {
            int s0 = __shfl_sync(0xffffffffu, myidx, jj);
            float4 v0 = __ldg((const float4*)(h + (size_t)s0 * 128) + lane);
            acc.x += v0.x; acc.y += v0.y; acc.z += v0.z; acc.w += v0.w;
        }
    }
    float r = 1.0f / (float)(cnt > 0 ? cnt : 1);
    acc.x *= r; acc.y *= r; acc.z *= r; acc.w *= r;
    *(float4*)(g_agg + (size_t)node * 128 + lane * 4) = acc;
}

// ============================ layer-2 gather on Zn (64 cols, halfwarp per node) ============================
// out[node] = Zs[node] + mean_src Zn[src] + b2  (pre-BN)
__global__ void __launch_bounds__(256)
gather_out_kernel(const float* __restrict__ Zs, const float* __restrict__ Zn,
                  const float* __restrict__ b2, float* __restrict__ out, int M) {
    int l16 = threadIdx.x & 15;
    int node = blockIdx.x * 16 + (threadIdx.x >> 4);
    if (node >= M) return;
    int beg = g_rowstart[node];
    int cnt = g_deg_i[node];
    float4 acc = make_float4(0.f, 0.f, 0.f, 0.f);
    for (int j0 = 0; j0 < cnt; j0 += 16) {
        int rem = cnt - j0;
        int lim = rem < 16 ? rem : 16;
        int myidx = (l16 < lim) ? __ldg(&g_csr_src[beg + j0 + l16]) : 0;
        int jj = 0;
        for (; jj + 4 <= lim; jj += 4) {
            int s0 = __shfl_sync(0xffffffffu, myidx, jj,     16);
            int s1 = __shfl_sync(0xffffffffu, myidx, jj + 1, 16);
            int s2 = __shfl_sync(0xffffffffu, myidx, jj + 2, 16);
            int s3 = __shfl_sync(0xffffffffu, myidx, jj + 3, 16);
            float4 v0 = __ldg((const float4*)(Zn + (size_t)s0 * 64) + l16);
            float4 v1 = __ldg((const float4*)(Zn + (size_t)s1 * 64) + l16);
            float4 v2 = __ldg((const float4*)(Zn + (size_t)s2 * 64) + l16);
            float4 v3 = __ldg((const float4*)(Zn + (size_t)s3 * 64) + l16);
            acc.x += (v0.x + v1.x) + (v2.x + v3.x);
            acc.y += (v0.y + v1.y) + (v2.y + v3.y);
            acc.z += (v0.z + v1.z) + (v2.z + v3.z);
            acc.w += (v0.w + v1.w) + (v2.w + v3.w);
        }
        for (; jj < lim; ++jj) {
            int s0 = __shfl_sync(0xffffffffu, myidx, jj, 16);
            float4 v0 = __ldg((const float4*)(Zn + (size_t)s0 * 64) + l16);
            acc.x += v0.x; acc.y += v0.y; acc.z += v0.z; acc.w += v0.w;
        }
    }
    float r = 1.0f / (float)(cnt > 0 ? cnt : 1);
    float4 zs = __ldg((const float4*)(Zs + (size_t)node * 64) + l16);
    float4 bb = __ldg((const float4*)b2 + l16);
    float4 y;
    y.x = fmaf(acc.x, r, zs.x) + bb.x;
    y.y = fmaf(acc.y, r, zs.y) + bb.y;
    y.z = fmaf(acc.z, r, zs.z) + bb.z;
    y.w = fmaf(acc.w, r, zs.w) + bb.w;
    *(float4*)(out + (size_t)node * 64 + l16 * 4) = y;
}

// ============================ layer-2 BN stats over out (few blocks, cheap atomics) ============================
__global__ void __launch_bounds__(256)
stats2_kernel(const float* __restrict__ out, int M) {
    __shared__ float ss[OUT_F], sq[OUT_F];
    int tid = threadIdx.x;
    if (tid < OUT_F) { ss[tid] = 0.f; sq[tid] = 0.f; }
    __syncthreads();
    long nvec = (long)M * 16;                         // float4 count
    long idx = (long)blockIdx.x * 256 + tid;
    long stride = (long)gridDim.x * 256;              // multiple of 16 -> col group fixed
    int colg = (int)(idx & 15);
    float4 s = make_float4(0.f, 0.f, 0.f, 0.f);
    float4 q = make_float4(0.f, 0.f, 0.f, 0.f);
    for (; idx < nvec; idx += stride) {
        float4 v = __ldg((const float4*)out + idx);
        s.x += v.x; s.y += v.y; s.z += v.z; s.w += v.w;
        q.x = fmaf(v.x, v.x, q.x); q.y = fmaf(v.y, v.y, q.y);
        q.z = fmaf(v.z, v.z, q.z); q.w = fmaf(v.w, v.w, q.w);
    }
    atomicAdd(&ss[colg * 4 + 0], s.x); atomicAdd(&ss[colg * 4 + 1], s.y);
    atomicAdd(&ss[colg * 4 + 2], s.z); atomicAdd(&ss[colg * 4 + 3], s.w);
    atomicAdd(&sq[colg * 4 + 0], q.x); atomicAdd(&sq[colg * 4 + 1], q.y);
    atomicAdd(&sq[colg * 4 + 2], q.z); atomicAdd(&sq[colg * 4 + 3], q.w);
    __syncthreads();
    if (tid < OUT_F) {
        atomicAdd(&g_fsum[tid],   ss[tid]);
        atomicAdd(&g_fsumsq[tid], sq[tid]);
    }
}

// ============================ persistent pipelined tcgen05 TS GEMM — layer 1 (R16, unchanged) ============================
#define STAGE_WORDS (128 * 65)
template <int NOUT, bool BNIN>
__global__ void __launch_bounds__(512) __cluster_dims__(1, 1, 1)
gemm_tc(const float* __restrict__ A, const float* __restrict__ Aneigh,
        const __nv_bfloat16* __restrict__ Bhi, const __nv_bfloat16* __restrict__ Blo,
        const float* __restrict__ bias, float* __restrict__ C, int M, int ntiles) {
#if HAS_TCGEN05
    extern __shared__ unsigned char smem_raw[];
    __shared__ uint32_t s_tmem[1];
    __shared__ __align__(8) unsigned long long s_mbar[1];

    const int tid = threadIdx.x;
    const int wid = tid >> 5;
    const int lane = tid & 31;
    constexpr int BBYTES = 8 * NOUT * 128;

    unsigned char* sB = (unsigned char*)(((uintptr_t)smem_raw + 1023) & ~(uintptr_t)1023);
    uint32_t* hiTile = (uint32_t*)(sB + BBYTES);
    uint32_t* loTile = hiTile + STAGE_WORDS;
    const uint32_t sB_addr = smem_u32(sB);
    const uint32_t tptr_addr = smem_u32(s_tmem);
    const uint32_t mbar_addr = smem_u32(s_mbar);
    const uint32_t warp_off = (uint32_t)(wid & 3) << 21;

    if (tid == 0) MBAR_INIT(mbar_addr, 1);

    for (int idx = tid; idx < 8 * NOUT * 8; idx += 512) {
        int c = idx / (NOUT * 8);
        int rem = idx - c * (NOUT * 8);
        int n = rem >> 3;
        int q = rem & 7;
        const __nv_bfloat16* s = ((q & 4) ? Blo : Bhi) + (size_t)n * 256 + c * 32 + (q & 3) * 8;
        uint4 val = *(const uint4*)s;
        uint32_t off = (uint32_t)(n * 128 + ((q & 4) ? 64 : 0) + (q & 3) * 16);
        *(uint4*)(sB + c * (NOUT * 128) + SW128(off)) = val;
    }

    if (wid == 0) TC_ALLOC(tptr_addr, 512);
    __syncthreads();
    if (wid == 0) TC_RELINQ();
    uint32_t tmem;
    asm volatile("ld.shared.b32 %0, [%1];" : "=r"(tmem) : "r"(tptr_addr));
    FENCE_ASYNC();
    __syncthreads();

    constexpr uint32_t IDESC =
        (1u << 4) | (1u << 7) | (1u << 10) | ((uint32_t)(NOUT / 8) << 17) | (8u << 24);
    const int myrow = tid & 127;
    const int sub = tid >> 7;
    int ph = 0;

    auto stage = [&](int row0, int p) {
        const float* __restrict__ srcM = p ? Aneigh : A;
        #pragma unroll
        for (int it = 0; it < 8; ++it) {
            int idx = tid + it * 512;
            int r = idx >> 5;
            int q = idx & 31;
            int gr = row0 + r;
            float4 v = make_float4(0.f, 0.f, 0.f, 0.f);
            if (gr < M) {
                v = *(const float4*)(srcM + (size_t)gr * 128 + q * 4);
                if (BNIN && p == 0) {
                    float4 sc = *(const float4*)(g_scale1 + q * 4);
                    float4 sh = *(const float4*)(g_shift1 + q * 4);
                    bn_relu4(v, sc, sh);
                }
            }
            uint32_t ux = __float_as_uint(v.x), uy = __float_as_uint(v.y);
            uint32_t uz = __float_as_uint(v.z), uw = __float_as_uint(v.w);
            uint32_t hi0 = __byte_perm(ux, uy, 0x7632);
            uint32_t hi1 = __byte_perm(uz, uw, 0x7632);
            float lx = v.x - __uint_as_float(ux & 0xFFFF0000u);
            float ly = v.y - __uint_as_float(uy & 0xFFFF0000u);
            float lz = v.z - __uint_as_float(uz & 0xFFFF0000u);
            float lw = v.w - __uint_as_float(uw & 0xFFFF0000u);
            uint32_t lo0 = __byte_perm(__float_as_uint(lx), __float_as_uint(ly), 0x7632);
            uint32_t lo1 = __byte_perm(__float_as_uint(lz), __float_as_uint(lw), 0x7632);
            int base = r * 65 + q * 2;
            hiTile[base] = hi0; hiTile[base + 1] = hi1;
            loTile[base] = lo0; loTile[base + 1] = lo1;
        }
    };
    auto tmemst = [&](int p) {
        uint32_t hr[16], lr[16];
        int base = myrow * 65 + sub * 16;
        #pragma unroll
        for (int i = 0; i < 16; ++i) { hr[i] = hiTile[base + i]; lr[i] = loTile[base + i]; }
        uint32_t col = (uint32_t)(p * 64 + sub * 16);
        TC_ST_X16(tmem + col + warp_off, hr);
        TC_ST_X16(tmem + 128 + col + warp_off, lr);
    };
    auto epilogue = [&](int row0, uint32_t d_tmem) {
        const int cset = wid >> 2;
        if (cset >= NOUT / 32) return;
        const int cbase = cset * 32;
        const int row = row0 + (wid & 3) * 32 + lane;
        const bool valid = (row < M);
        uint32_t dr[32];
        TC_LD_X32(dr, d_tmem + cbase);
        TC_WAIT_LD();
        float s[32], q[32];
        #pragma unroll
        for (int j = 0; j < 32; ++j) {
            float y = __uint_as_float(dr[j]) + __ldg(&bias[cbase + j]);
            s[j] = valid ? y : 0.f;
            q[j] = valid ? y * y : 0.f;
            dr[j] = __float_as_uint(y);
        }
        if (valid) {
            #pragma unroll
            for (int j = 0; j < 32; j += 4)
                *(float4*)(C + (size_t)row * NOUT + cbase + j) =
                    make_float4(__uint_as_float(dr[j]), __uint_as_float(dr[j + 1]),
                                __uint_as_float(dr[j + 2]), __uint_as_float(dr[j + 3]));
        }
        #pragma unroll
        for (int half = 16; half >= 1; half >>= 1) {
            bool up = (lane & half) != 0;
            #pragma unroll
            for (int j = 0; j < half; ++j) {
                float ssend = up ? s[j] : s[j + half];
                float qsend = up ? q[j] : q[j + half];
                float srecv = __shfl_xor_sync(0xffffffffu, ssend, half);
                float qrecv = __shfl_xor_sync(0xffffffffu, qsend, half);
                s[j] = (up ? s[j + half] : s[j]) + srecv;
                q[j] = (up ? q[j + half] : q[j]) + qrecv;
            }
        }
        atomicAdd(&g_fsum[cbase + lane], s[0]);
        atomicAdd(&g_fsumsq[cbase + lane], q[0]);
    };

    int tile = blockIdx.x;
    int pend_row0 = 0;
    int pendbuf = 0;
    int curbuf = 0;
    bool have_pending = false;
    if (tile < ntiles) stage(tile * 128, 0);
    __syncthreads();

    while (tile < ntiles) {
        const int row0 = tile * 128;
        if (have_pending) {
            MBAR_WAIT(mbar_addr, ph);
            ph ^= 1;
            TC_FENCE_AFTER();
        }
        __syncthreads();
        tmemst(0);
        __syncthreads();
        stage(row0, 1);
        __syncthreads();
        tmemst(1);
        TC_WAIT_ST();
        TC_FENCE_BEFORE();
        __syncthreads();
        const uint32_t d_cur = tmem + 256 + (uint32_t)curbuf * NOUT;
        if (wid == 0) {
            TC_FENCE_AFTER();
            if (elect_one()) {
                #pragma unroll
                for (int t = 0; t < 16; ++t) {
                    int c = t >> 1, ss = t & 1;
                    uint64_t dhi = make_desc(sB_addr + c * (NOUT * 128)) + 2 * ss;
                    uint64_t dlo = dhi + 4;
                    mma_f16_ts(d_cur, tmem + t * 8,       dhi, IDESC, t > 0);
                    mma_f16_ts(d_cur, tmem + t * 8,       dlo, IDESC, true);
                    mma_f16_ts(d_cur, tmem + 128 + t * 8, dhi, IDESC, true);
                }
                TC_COMMIT(mbar_addr);
            }
        }
        if (have_pending) epilogue(pend_row0, tmem + 256 + (uint32_t)pendbuf * NOUT);
        pend_row0 = row0;
        pendbuf = curbuf;
        curbuf ^= 1;
        have_pending = true;
        tile += gridDim.x;
        if (tile < ntiles) stage(tile * 128, 0);
        __syncthreads();
    }
    if (have_pending) {
        MBAR_WAIT(mbar_addr, ph);
        ph ^= 1;
        TC_FENCE_AFTER();
        epilogue(pend_row0, tmem + 256 + (uint32_t)pendbuf * NOUT);
    }
    __syncthreads();
    if (tid == 0) MBAR_INVAL(mbar_addr);
    if (wid == 0) TC_DEALLOC(tmem, 512);
#else
    const int tid = threadIdx.x;
    for (int tile = blockIdx.x; tile < ntiles; tile += gridDim.x) {
        const int row = tile * 128 + (tid & 127);
        if (tid < 128 && row < M) {
            float acc[NOUT];
            #pragma unroll
            for (int n = 0; n < NOUT; ++n) acc[n] = 0.f;
            for (int k = 0; k < 256; ++k) {
                float a;
                if (k < 128) {
                    a = A[(size_t)row * 128 + k];
                    if (BNIN) a = fmaxf(fmaf(a, g_scale1[k], g_shift1[k]), 0.f);
                } else {
                    a = Aneigh[(size_t)row * 128 + (k - 128)];
                }
                for (int n = 0; n < NOUT; ++n) {
                    float w = __bfloat162float(Bhi[(size_t)n * 256 + k]) +
                              __bfloat162float(Blo[(size_t)n * 256 + k]);
                    acc[n] += a * w;
                }
            }
            for (int n = 0; n < NOUT; ++n) {
                float y = acc[n] + bias[n];
                C[(size_t)row * NOUT + n] = y;
                atomicAdd(&g_fsum[n], y);
                atomicAdd(&g_fsumsq[n], y * y);
            }
        }
    }
#endif
}

// ============================ layer-2 GEMM: Z = relu(bn(h1)) @ [Ws2|Wn2], K=128 ============================
// Single-pass A (BN+ReLU), 24 MMAs/tile, split outputs Zs (cols 0-63) / Zn (cols 64-127).
__global__ void __launch_bounds__(512) __cluster_dims__(1, 1, 1)
gemm2_tc(const float* __restrict__ A,
         const __nv_bfloat16* __restrict__ Bhi, const __nv_bfloat16* __restrict__ Blo,
         float* __restrict__ Zs, float* __restrict__ Zn, int M, int ntiles) {
#if HAS_TCGEN05
    extern __shared__ unsigned char smem_raw[];
    __shared__ uint32_t s_tmem[1];
    __shared__ __align__(8) unsigned long long s_mbar[1];

    const int tid = threadIdx.x;
    const int wid = tid >> 5;
    const int lane = tid & 31;
    constexpr int NOUT = 128;
    constexpr int BBYTES = 4 * NOUT * 128;       // 4 k-chunks

    unsigned char* sB = (unsigned char*)(((uintptr_t)smem_raw + 1023) & ~(uintptr_t)1023);
    uint32_t* hiTile = (uint32_t*)(sB + BBYTES);
    uint32_t* loTile = hiTile + STAGE_WORDS;
    const uint32_t sB_addr = smem_u32(sB);
    const uint32_t tptr_addr = smem_u32(s_tmem);
    const uint32_t mbar_addr = smem_u32(s_mbar);
    const uint32_t warp_off = (uint32_t)(wid & 3) << 21;

    if (tid == 0) MBAR_INIT(mbar_addr, 1);

    // B load once: 4 chunk-tiles of 128 rows x 128B ([hi 64|lo 64]), SW128
    for (int idx = tid; idx < 4 * NOUT * 8; idx += 512) {
        int c = idx / (NOUT * 8);
        int rem = idx - c * (NOUT * 8);
        int n = rem >> 3;
        int q = rem & 7;
        const __nv_bfloat16* s = ((q & 4) ? Blo : Bhi) + (size_t)n * 128 + c * 32 + (q & 3) * 8;
        uint4 val = *(const uint4*)s;
        uint32_t off = (uint32_t)(n * 128 + ((q & 4) ? 64 : 0) + (q & 3) * 16);
        *(uint4*)(sB + c * (NOUT * 128) + SW128(off)) = val;
    }

    if (wid == 0) TC_ALLOC(tptr_addr, 512);
    __syncthreads();
    if (wid == 0) TC_RELINQ();
    uint32_t tmem;
    asm volatile("ld.shared.b32 %0, [%1];" : "=r"(tmem) : "r"(tptr_addr));
    FENCE_ASYNC();
    __syncthreads();

    constexpr uint32_t IDESC =
        (1u << 4) | (1u << 7) | (1u << 10) | ((uint32_t)(NOUT / 8) << 17) | (8u << 24);
    const int myrow = tid & 127;
    const int sub = tid >> 7;
    int ph = 0;

    auto stage = [&](int row0) {
        #pragma unroll
        for (int it = 0; it < 8; ++it) {
            int idx = tid + it * 512;
            int r = idx >> 5;
            int q = idx & 31;
            int gr = row0 + r;
            float4 v = make_float4(0.f, 0.f, 0.f, 0.f);
            if (gr < M) {
                v = *(const float4*)(A + (size_t)gr * 128 + q * 4);
                float4 sc = *(const float4*)(g_scale1 + q * 4);
                float4 sh = *(const float4*)(g_shift1 + q * 4);
                bn_relu4(v, sc, sh);
            }
            uint32_t ux = __float_as_uint(v.x), uy = __float_as_uint(v.y);
            uint32_t uz = __float_as_uint(v.z), uw = __float_as_uint(v.w);
            uint32_t hi0 = __byte_perm(ux, uy, 0x7632);
            uint32_t hi1 = __byte_perm(uz, uw, 0x7632);
            float lx = v.x - __uint_as_float(ux & 0xFFFF0000u);
            float ly = v.y - __uint_as_float(uy & 0xFFFF0000u);
            float lz = v.z - __uint_as_float(uz & 0xFFFF0000u);
            float lw = v.w - __uint_as_float(uw & 0xFFFF0000u);
            uint32_t lo0 = __byte_perm(__float_as_uint(lx), __float_as_uint(ly), 0x7632);
            uint32_t lo1 = __byte_perm(__float_as_uint(lz), __float_as_uint(lw), 0x7632);
            int base = r * 65 + q * 2;
            hiTile[base] = hi0; hiTile[base + 1] = hi1;
            loTile[base] = lo0; loTile[base + 1] = lo1;
        }
    };
    auto tmemst = [&]() {                          // A-hi cols [0,64), A-lo [128,192)
        uint32_t hr[16], lr[16];
        int base = myrow * 65 + sub * 16;
        #pragma unroll
        for (int i = 0; i < 16; ++i) { hr[i] = hiTile[base + i]; lr[i] = loTile[base + i]; }
        uint32_t col = (uint32_t)(sub * 16);
        TC_ST_X16(tmem + col + warp_off, hr);
        TC_ST_X16(tmem + 128 + col + warp_off, lr);
    };
    auto epilogue = [&](int row0, uint32_t d_tmem) {
        const int cset = wid >> 2;                 // 0..3
        const int cbase = cset * 32;
        const int row = row0 + (wid & 3) * 32 + lane;
        const bool valid = (row < M);
        uint32_t dr[32];
        TC_LD_X32(dr, d_tmem + cbase);
        TC_WAIT_LD();
        if (valid) {
            float* dstrow = (cbase < 64) ? (Zs + (size_t)row * 64 + cbase)
                                         : (Zn + (size_t)row * 64 + (cbase - 64));
            #pragma unroll
            for (int j = 0; j < 32; j += 4)
                *(float4*)(dstrow + j) =
                    make_float4(__uint_as_float(dr[j]), __uint_as_float(dr[j + 1]),
                                __uint_as_float(dr[j + 2]), __uint_as_float(dr[j + 3]));
        }
    };

    int tile = blockIdx.x;
    int pend_row0 = 0;
    int pendbuf = 0;
    int curbuf = 0;
    bool have_pending = false;
    if (tile < ntiles) stage(tile * 128);
    __syncthreads();

    while (tile < ntiles) {
        if (have_pending) {
            MBAR_WAIT(mbar_addr, ph);
            ph ^= 1;
            TC_FENCE_AFTER();
        }
        __syncthreads();
        tmemst();
        TC_WAIT_ST();
        TC_FENCE_BEFORE();
        __syncthreads();
        const uint32_t d_cur = tmem + 256 + (uint32_t)curbuf * NOUT;
        if (wid == 0) {
            TC_FENCE_AFTER();
            if (elect_one()) {
                #pragma unroll
                for (int t = 0; t < 8; ++t) {
                    int c = t >> 1, ss = t & 1;
                    uint64_t dhi = make_desc(sB_addr + c * (NOUT * 128)) + 2 * ss;
                    uint64_t dlo = dhi + 4;
                    mma_f16_ts(d_cur, tmem + t * 8,       dhi, IDESC, t > 0);
                    mma_f16_ts(d_cur, tmem + t * 8,       dlo, IDESC, true);
                    mma_f16_ts(d_cur, tmem + 128 + t * 8, dhi, IDESC, true);
                }
                TC_COMMIT(mbar_addr);
            }
        }
        if (have_pending) epilogue(pend_row0, tmem + 256 + (uint32_t)pendbuf * NOUT);
        pend_row0 = tile * 128;
        pendbuf = curbuf;
        curbuf ^= 1;
        have_pending = true;
        tile += gridDim.x;
        if (tile < ntiles) stage(tile * 128);      // overlaps MMA in flight
        __syncthreads();
    }
    if (have_pending) {
        MBAR_WAIT(mbar_addr, ph);
        ph ^= 1;
        TC_FENCE_AFTER();
        epilogue(pend_row0, tmem + 256 + (uint32_t)pendbuf * NOUT);
    }
    __syncthreads();
    if (tid == 0) MBAR_INVAL(mbar_addr);
    if (wid == 0) TC_DEALLOC(tmem, 512);
#else
    // SIMT fallback (plain compute_103 PTX pass; never selected at runtime)
    const int tid = threadIdx.x;
    for (int tile = blockIdx.x; tile < ntiles; tile += gridDim.x) {
        const int row = tile * 128 + (tid & 127);
        if (tid < 128 && row < M) {
            float acc[128];
            #pragma unroll
            for (int n = 0; n < 128; ++n) acc[n] = 0.f;
            for (int k = 0; k < 128; ++k) {
                float a = A[(size_t)row * 128 + k];
                a = fmaxf(fmaf(a, g_scale1[k], g_shift1[k]), 0.f);
                for (int n = 0; n < 128; ++n) {
                    float w = __bfloat162float(Bhi[(size_t)n * 128 + k]) +
                              __bfloat162float(Blo[(size_t)n * 128 + k]);
                    acc[n] += a * w;
                }
            }
            for (int n = 0; n < 64; ++n) Zs[(size_t)row * 64 + n] = acc[n];
            for (int n = 64; n < 128; ++n) Zn[(size_t)row * 64 + (n - 64)] = acc[n];
        }
    }
#endif
}

// ============================ BN prep (zeroes stats after reading) ============================
template <int COLS, int LAYER>
__global__ void bnprep_kernel(const float* __restrict__ gamma,
                              const float* __restrict__ beta, int M) {
    int c = threadIdx.x;
    if (c >= COLS) return;
    float invM = 1.0f / (float)M;
    float mu = g_fsum[c] * invM;
    float var = g_fsumsq[c] * invM - mu * mu;
    if (var < 0.f) var = 0.f;
    float sc = gamma[c] * rsqrtf(var + EPS);
    if (LAYER == 1) { g_scale1[c] = sc; g_shift1[c] = beta[c] - mu * sc; }
    else            { g_scale2[c] = sc; g_shift2[c] = beta[c] - mu * sc; }
    g_fsum[c] = 0.f;
    g_fsumsq[c] = 0.f;
}
__global__ void apply_out_kernel(float* __restrict__ h, long total) {
    long i = ((long)blockIdx.x * blockDim.x + threadIdx.x) * 4;
    long stride = (long)gridDim.x * blockDim.x * 4;
    for (; i < total; i += stride) {
        int c = (int)(i & (OUT_F - 1));
        float4 v = *(float4*)(h + i);
        float4 sc = *(const float4*)(g_scale2 + c);
        float4 sh = *(const float4*)(g_shift2 + c);
        v.x = fmaf(v.x, sc.x, sh.x);
        v.y = fmaf(v.y, sc.y, sh.y);
        v.z = fmaf(v.z, sc.z, sh.z);
        v.w = fmaf(v.w, sc.w, sh.w);
        *(float4*)(h + i) = v;
    }
}

// ============================ launch ============================
extern "C" void kernel_launch(void* const* d_in, const int* in_sizes, int n_in,
                              void* d_out, int out_size) {
    const float* features = (const float*)d_in[0];
    const int*   src      = (const int*)d_in[1];
    const int*   dst      = (const int*)d_in[2];
    const float* W_self1  = (const float*)d_in[3];
    const float* W_neigh1 = (const float*)d_in[4];
    const float* b1       = (const float*)d_in[5];
    const float* gamma1   = (const float*)d_in[6];
    const float* beta1    = (const float*)d_in[7];
    const float* W_self2  = (const float*)d_in[8];
    const float* W_neigh2 = (const float*)d_in[9];
    const float* b2       = (const float*)d_in[10];
    const float* gamma2   = (const float*)d_in[11];
    const float* beta2    = (const float*)d_in[12];
    float* out = (float*)d_out;

    const int M = in_sizes[0] / IN_F;
    const int E = in_sizes[1];

    void *p_deg, *p_agg, *p_h1, *p_b1hi, *p_b1lo, *p_b2hi, *p_b2lo;
    cudaGetSymbolAddress(&p_deg, g_deg_i);
    cudaGetSymbolAddress(&p_agg, g_agg);
    cudaGetSymbolAddress(&p_h1, g_h1);
    cudaGetSymbolAddress(&p_b1hi, g_B1hi);
    cudaGetSymbolAddress(&p_b1lo, g_B1lo);
    cudaGetSymbolAddress(&p_b2hi, g_B2hi);
    cudaGetSymbolAddress(&p_b2lo, g_B2lo);
    float* agg = (float*)p_agg;
    float* h1  = (float*)p_h1;
    float* Zs  = agg;                               // [M,64]
    float* Zn  = agg + (size_t)N_NODES * 64;        // [M,64]

    const int eb = (E + 255) / 256;
    const int gatherBlocks = (M + 7) / 8;
    const int gatherOutBlocks = (M + 15) / 16;
    const int ntiles = (M + 127) / 128;
    const int gemmGrid = ntiles < 148 ? ntiles : 148;

    const int stageBytes = 2 * STAGE_WORDS * 4;                 // 66560
    const int smem1 = 8 * HID_F * 128 + stageBytes + 1024;     // 198656
    const int smem2 = 4 * 128 * 128 + stageBytes + 1024;       // 133120
    cudaFuncSetAttribute(gemm_tc<HID_F, false>,
                         cudaFuncAttributeMaxDynamicSharedMemorySize, smem1);
    cudaFuncSetAttribute(gemm2_tc,
                         cudaFuncAttributeMaxDynamicSharedMemorySize, smem2);

    // CSR build (+ fused weight split & stat zero)
    cudaMemsetAsync(p_deg, 0, (size_t)(N_NODES + 1) * sizeof(int), 0);
    hist_kernel<<<eb, 256>>>(dst, E);
    alloc_kernel<<<(M + 255) / 256, 256>>>(M, W_self1, W_neigh1, W_self2, W_neigh2);
    fill_kernel<<<eb, 256>>>(src, dst, E);

    // ---- layer 1 ----
    gather_kernel<<<gatherBlocks, 256>>>(features, M);
    gemm_tc<HID_F, false><<<gemmGrid, 512, smem1>>>(features, agg,
        (const __nv_bfloat16*)p_b1hi, (const __nv_bfloat16*)p_b1lo, b1, h1, M, ntiles);
    bnprep_kernel<HID_F, 1><<<1, HID_F>>>(gamma1, beta1, M);

    // ---- layer 2: Z = relu(bn(h1)) @ [Ws2|Wn2]; assemble via 64-col gather ----
    gemm2_tc<<<gemmGrid, 512, smem2>>>(h1,
        (const __nv_bfloat16*)p_b2hi, (const __nv_bfloat16*)p_b2lo, Zs, Zn, M, ntiles);
    gather_out_kernel<<<gatherOutBlocks, 256>>>(Zs, Zn, b2, out, M);
    stats2_kernel<<<296, 256>>>(out, M);
    bnprep_kernel<OUT_F, 2><<<1, OUT_F>>>(gamma2, beta2, M);
    apply_out_kernel<<<2048, 256>>>(out, (long)M * OUT_F);
}